// round 2
// baseline (speedup 1.0000x reference)
#include <cuda_runtime.h>
#include <math.h>

// Problem constants
#define Bv   8
#define Sv   2048
#define Dv   1024
#define Hv   16
#define HDv  64
#define HIDv 256
#define BHv  128               // B*H
#define Mv   (Bv*Sv)           // 16384 rows of x
#define MTv  (BHv*Sv)          // 262144 rows per-head

// ------------------------- scratch (device globals) -------------------------
__device__ float g_xn[Mv*Dv];          // 64 MB  (store-norm, then retrieve-norm)
__device__ float g_keys[MTv*HDv];      // 64 MB  (split-head)
__device__ float g_values[MTv*HDv];    // 64 MB
__device__ float g_q[MTv*HDv];         // 64 MB
__device__ float g_pre0[MTv*HIDv];     // 256 MB (pre-act, then dh0 in place)
__device__ float g_h1[MTv*HIDv];       // 256 MB (gelu act; reused in retrieve)
__device__ float g_pre1[MTv*HDv];      // 64 MB (reused in retrieve)
__device__ float g_dh[MTv*HDv];        // 64 MB
__device__ float g_alpha[BHv*Sv];
__device__ float g_theta[BHv*Sv];
__device__ float g_amean[BHv];
__device__ float g_coef[BHv];
__device__ float g_g0[BHv*HDv*HIDv];   // 8 MB
__device__ float g_g1[BHv*HIDv*HDv];   // 8 MB
__device__ float g_nW0[BHv*HDv*HIDv];
__device__ float g_nW1[BHv*HIDv*HDv];

// ------------------------- rmsnorm over D=1024 rows -------------------------
__global__ void k_rmsnorm_row(const float* __restrict__ x, const float* __restrict__ w,
                              float* __restrict__ y) {
    int row = blockIdx.x;
    const float* xr = x + (size_t)row * Dv;
    float* yr = y + (size_t)row * Dv;
    int tid = threadIdx.x;  // 256
    float v[4]; float ss = 0.f;
#pragma unroll
    for (int i = 0; i < 4; i++) { v[i] = xr[tid + i*256]; ss += v[i]*v[i]; }
#pragma unroll
    for (int o = 16; o > 0; o >>= 1) ss += __shfl_xor_sync(0xffffffffu, ss, o);
    __shared__ float red[8];
    __shared__ float rinv;
    if ((tid & 31) == 0) red[tid >> 5] = ss;
    __syncthreads();
    if (tid == 0) {
        float t = 0.f;
#pragma unroll
        for (int i = 0; i < 8; i++) t += red[i];
        rinv = rsqrtf(t / (float)Dv + 1e-6f);
    }
    __syncthreads();
    float r = rinv;
#pragma unroll
    for (int i = 0; i < 4; i++) yr[tid + i*256] = v[i] * w[tid + i*256] * r;
}

// ------------------------- rmsnorm over 64-wide rows, in place --------------
__global__ void k_rmsnorm64(float* __restrict__ x, const float* __restrict__ w) {
    int r = blockIdx.x * 8 + (threadIdx.x >> 5);
    int lane = threadIdx.x & 31;
    float* xr = x + (size_t)r * 64;
    float a = xr[lane], b = xr[lane + 32];
    float ss = a*a + b*b;
#pragma unroll
    for (int o = 16; o > 0; o >>= 1) ss += __shfl_xor_sync(0xffffffffu, ss, o);
    float rr = rsqrtf(ss / 64.f + 1e-6f);
    xr[lane]      = a * w[lane]      * rr;
    xr[lane + 32] = b * w[lane + 32] * rr;
}

// ----------------- big SGEMM: (16384x1024)@(1024x1024), split-head out ------
__global__ void __launch_bounds__(256)
k_sgemm_splithead(const float* __restrict__ A, const float* __restrict__ B,
                  float* __restrict__ C) {
    __shared__ float As[16][128];
    __shared__ float Bs[16][128];
    int bm = blockIdx.y, bn = blockIdx.x;
    int tid = threadIdx.x;
    int ty = tid >> 4, tx = tid & 15;
    const int m0 = bm * 128, n0 = bn * 128;
    float acc[8][8] = {};
    for (int k0 = 0; k0 < 1024; k0 += 16) {
#pragma unroll
        for (int i = 0; i < 2; i++) {
            int idx = tid + i*256;            // 0..511
            int r = idx >> 2, c4 = idx & 3;
            float4 v = *(const float4*)(A + (size_t)(m0 + r)*1024 + k0 + c4*4);
            As[c4*4+0][r] = v.x; As[c4*4+1][r] = v.y;
            As[c4*4+2][r] = v.z; As[c4*4+3][r] = v.w;
        }
#pragma unroll
        for (int i = 0; i < 2; i++) {
            int idx = tid + i*256;
            int r = idx >> 5, c4 = idx & 31;
            *(float4*)&Bs[r][c4*4] = *(const float4*)(B + (size_t)(k0 + r)*1024 + n0 + c4*4);
        }
        __syncthreads();
#pragma unroll
        for (int k = 0; k < 16; k++) {
            float ra[8], rb[8];
#pragma unroll
            for (int i = 0; i < 8; i++) ra[i] = As[k][ty*8 + i];
#pragma unroll
            for (int j = 0; j < 8; j++) rb[j] = Bs[k][tx*8 + j];
#pragma unroll
            for (int i = 0; i < 8; i++)
#pragma unroll
                for (int j = 0; j < 8; j++) acc[i][j] += ra[i] * rb[j];
        }
        __syncthreads();
    }
#pragma unroll
    for (int i = 0; i < 8; i++) {
        int m = m0 + ty*8 + i;
        int b = m >> 11, s = m & 2047;
#pragma unroll
        for (int j = 0; j < 8; j++) {
            int n = n0 + tx*8 + j;
            int h = n >> 6, hd = n & 63;
            C[(((size_t)(b*Hv + h))*Sv + s)*64 + hd] = acc[i][j];
        }
    }
}

// -------- K=64 GEMM: (MT x 64) @ (64 x 256), optional batched weight --------
// MODE 0: forward. write raw pre to out1 (if non-null) and gelu(pre) to out2.
// MODE 1: dh0. B accessed transposed (W is 256x64); multiply by gelu'(aux) where
//         aux = out2 (pre0); write to out1 (may alias out2: same-thread same-off).
template <int MODE>
__global__ void __launch_bounds__(256)
k_gemm_k64(const float* __restrict__ A, const float* __restrict__ W,
           long long wstride, float* __restrict__ out1, float* __restrict__ out2) {
    __shared__ float As[64][128];
    __shared__ float Bs[64][64];
    int bm = blockIdx.y, bn = blockIdx.x;
    int tid = threadIdx.x;
    int m0 = bm * 128, n0 = bn * 64;
    int bh = m0 >> 11;
    const float* Wp = W + (size_t)bh * wstride;
#pragma unroll
    for (int i = 0; i < 8; i++) {
        int idx = tid + i*256;                // 0..2047
        int r = idx >> 4, c4 = idx & 15;
        float4 v = *(const float4*)(A + (size_t)(m0 + r)*64 + c4*4);
        As[c4*4+0][r] = v.x; As[c4*4+1][r] = v.y;
        As[c4*4+2][r] = v.z; As[c4*4+3][r] = v.w;
    }
    if (MODE == 0) {
#pragma unroll
        for (int i = 0; i < 4; i++) {
            int idx = tid + i*256;            // 0..1023
            int r = idx >> 4, c4 = idx & 15;
            *(float4*)&Bs[r][c4*4] = *(const float4*)(Wp + (size_t)r*256 + n0 + c4*4);
        }
    } else {
#pragma unroll
        for (int i = 0; i < 4; i++) {
            int idx = tid + i*256;
            int n = idx >> 4, c4 = idx & 15;
            float4 v = *(const float4*)(Wp + (size_t)(n0 + n)*64 + c4*4);
            Bs[c4*4+0][n] = v.x; Bs[c4*4+1][n] = v.y;
            Bs[c4*4+2][n] = v.z; Bs[c4*4+3][n] = v.w;
        }
    }
    __syncthreads();
    int ty = tid >> 4, tx = tid & 15;
    float acc[8][4] = {};
#pragma unroll
    for (int k = 0; k < 64; k++) {
        float ra[8], rb[4];
#pragma unroll
        for (int i = 0; i < 8; i++) ra[i] = As[k][ty*8 + i];
#pragma unroll
        for (int j = 0; j < 4; j++) rb[j] = Bs[k][tx*4 + j];
#pragma unroll
        for (int i = 0; i < 8; i++)
#pragma unroll
            for (int j = 0; j < 4; j++) acc[i][j] += ra[i] * rb[j];
    }
#pragma unroll
    for (int i = 0; i < 8; i++) {
        size_t m = (size_t)m0 + ty*8 + i;
#pragma unroll
        for (int j = 0; j < 4; j++) {
            int n = n0 + tx*4 + j;
            size_t off = m*256 + n;
            float v = acc[i][j];
            if (MODE == 0) {
                if (out1) out1[off] = v;
                out2[off] = 0.5f * v * (1.f + erff(v * 0.70710678118654752f));
            } else {
                float p = out2[off];
                float cdf = 0.5f * (1.f + erff(p * 0.70710678118654752f));
                float pdf = expf(-0.5f * p * p) * 0.3989422804014327f;
                out1[off] = v * (cdf + p * pdf);
            }
        }
    }
}

// -------- K=256 GEMM: (MT x 256) @ (256 x 64), optional batched weight ------
__global__ void __launch_bounds__(256)
k_gemm_k256(const float* __restrict__ A, const float* __restrict__ W,
            long long wstride, float* __restrict__ C) {
    __shared__ float As[32][128];
    __shared__ float Bs[32][64];
    int bm = blockIdx.x;
    int tid = threadIdx.x;
    int m0 = bm * 128;
    int bh = m0 >> 11;
    const float* Wp = W + (size_t)bh * wstride;
    int ty = tid >> 4, tx = tid & 15;
    float acc[8][4] = {};
    for (int k0 = 0; k0 < 256; k0 += 32) {
#pragma unroll
        for (int i = 0; i < 4; i++) {
            int idx = tid + i*256;            // 0..1023
            int r = idx >> 3, c4 = idx & 7;
            float4 v = *(const float4*)(A + (size_t)(m0 + r)*256 + k0 + c4*4);
            As[c4*4+0][r] = v.x; As[c4*4+1][r] = v.y;
            As[c4*4+2][r] = v.z; As[c4*4+3][r] = v.w;
        }
#pragma unroll
        for (int i = 0; i < 2; i++) {
            int idx = tid + i*256;            // 0..511
            int r = idx >> 4, c4 = idx & 15;
            *(float4*)&Bs[r][c4*4] = *(const float4*)(Wp + (size_t)(k0 + r)*64 + c4*4);
        }
        __syncthreads();
#pragma unroll
        for (int k = 0; k < 32; k++) {
            float ra[8], rb[4];
#pragma unroll
            for (int i = 0; i < 8; i++) ra[i] = As[k][ty*8 + i];
#pragma unroll
            for (int j = 0; j < 4; j++) rb[j] = Bs[k][tx*4 + j];
#pragma unroll
            for (int i = 0; i < 8; i++)
#pragma unroll
                for (int j = 0; j < 4; j++) acc[i][j] += ra[i] * rb[j];
        }
        __syncthreads();
    }
#pragma unroll
    for (int i = 0; i < 8; i++) {
        size_t m = (size_t)m0 + ty*8 + i;
#pragma unroll
        for (int j = 0; j < 4; j++) C[m*64 + tx*4 + j] = acc[i][j];
    }
}

// ---------- fused pf_rmsnorm fwd+bwd for the store loss gradient ------------
__global__ void k_dh() {
    int r = blockIdx.x * 8 + (threadIdx.x >> 5);
    int lane = threadIdx.x & 31;
    size_t base = (size_t)r * 64;
    float h0 = g_pre1[base + lane], h1 = g_pre1[base + lane + 32];
    float ss = h0*h0 + h1*h1;
#pragma unroll
    for (int o = 16; o > 0; o >>= 1) ss += __shfl_xor_sync(0xffffffffu, ss, o);
    float rms = sqrtf(ss / 64.f + 1e-8f);
    float hn0 = h0 / rms, hn1 = h1 / rms;
    float t = g_theta[r];
    float dp0 = 2.f * t * ((hn0 + g_keys[base + lane])      - g_values[base + lane]);
    float dp1 = 2.f * t * ((hn1 + g_keys[base + lane + 32]) - g_values[base + lane + 32]);
    float dy = dp0*hn0 + dp1*hn1;
#pragma unroll
    for (int o = 16; o > 0; o >>= 1) dy += __shfl_xor_sync(0xffffffffu, dy, o);
    g_dh[base + lane]      = (dp0 - hn0 * dy / 64.f) / rms;
    g_dh[base + lane + 32] = (dp1 - hn1 * dy / 64.f) / rms;
}

// ---------------- batched A^T B weight-gradient GEMM ------------------------
// G[bh, i, o] = sum_s A[bh*S+s, i] * Bm[bh*S+s, o]
template <int I, int O>
__global__ void __launch_bounds__(256)
k_gradT(const float* __restrict__ A, const float* __restrict__ Bm,
        float* __restrict__ G) {
    __shared__ float At[32][64];
    __shared__ float Bt[32][64];
    int bh = blockIdx.z;
    int i0 = blockIdx.y * 64, o0 = blockIdx.x * 64;
    int tid = threadIdx.x;
    int ty = tid >> 4, tx = tid & 15;
    float acc[4][4] = {};
    const float* Ab = A  + (size_t)bh * Sv * I;
    const float* Bb = Bm + (size_t)bh * Sv * O;
    for (int s0 = 0; s0 < Sv; s0 += 32) {
#pragma unroll
        for (int i = 0; i < 2; i++) {
            int idx = tid + i*256;            // 0..511
            int r = idx >> 4, c4 = idx & 15;
            *(float4*)&At[r][c4*4] = *(const float4*)(Ab + (size_t)(s0 + r)*I + i0 + c4*4);
            *(float4*)&Bt[r][c4*4] = *(const float4*)(Bb + (size_t)(s0 + r)*O + o0 + c4*4);
        }
        __syncthreads();
#pragma unroll
        for (int k = 0; k < 32; k++) {
            float ra[4], rb[4];
#pragma unroll
            for (int i = 0; i < 4; i++) ra[i] = At[k][ty*4 + i];
#pragma unroll
            for (int j = 0; j < 4; j++) rb[j] = Bt[k][tx*4 + j];
#pragma unroll
            for (int i = 0; i < 4; i++)
#pragma unroll
                for (int j = 0; j < 4; j++) acc[i][j] += ra[i] * rb[j];
        }
        __syncthreads();
    }
#pragma unroll
    for (int i = 0; i < 4; i++)
#pragma unroll
        for (int j = 0; j < 4; j++)
            G[((size_t)bh*I + i0 + ty*4 + i)*O + o0 + tx*4 + j] = acc[i][j];
}

// ---------------- gates: alpha, theta (sigmoid) in (BH, S) layout -----------
__global__ void __launch_bounds__(256)
k_gates(const float* __restrict__ aw, const float* __restrict__ ab,
        const float* __restrict__ tw, const float* __restrict__ tb) {
    __shared__ float Xs[64][128];   // [k][row]
    __shared__ float Ws[64][32];    // cols 0..15 alpha, 16..31 theta
    int m0 = blockIdx.x * 128;
    int tid = threadIdx.x;
    int rg = tid >> 3, cg = tid & 7;     // rows rg*4.., cols cg*4..
    float acc[4][4] = {};
    for (int k0 = 0; k0 < 1024; k0 += 64) {
#pragma unroll
        for (int i = 0; i < 8; i++) {
            int idx = tid + i*256;        // 0..2047
            int r = idx >> 4, c4 = idx & 15;
            float4 v = *(const float4*)(g_xn + (size_t)(m0 + r)*1024 + k0 + c4*4);
            Xs[c4*4+0][r] = v.x; Xs[c4*4+1][r] = v.y;
            Xs[c4*4+2][r] = v.z; Xs[c4*4+3][r] = v.w;
        }
#pragma unroll
        for (int i = 0; i < 2; i++) {
            int idx = tid + i*256;        // 0..511
            int r = idx >> 3, c4 = idx & 7;
            const float* src = (c4 < 4) ? (aw + (size_t)(k0 + r)*16 + c4*4)
                                        : (tw + (size_t)(k0 + r)*16 + (c4 - 4)*4);
            *(float4*)&Ws[r][c4*4] = *(const float4*)src;
        }
        __syncthreads();
#pragma unroll
        for (int k = 0; k < 64; k++) {
            float ra[4], rb[4];
#pragma unroll
            for (int i = 0; i < 4; i++) ra[i] = Xs[k][rg*4 + i];
#pragma unroll
            for (int j = 0; j < 4; j++) rb[j] = Ws[k][cg*4 + j];
#pragma unroll
            for (int i = 0; i < 4; i++)
#pragma unroll
                for (int j = 0; j < 4; j++) acc[i][j] += ra[i] * rb[j];
        }
        __syncthreads();
    }
#pragma unroll
    for (int i = 0; i < 4; i++) {
        int m = m0 + rg*4 + i;
        int b = m >> 11, s = m & 2047;
#pragma unroll
        for (int j = 0; j < 4; j++) {
            int c = cg*4 + j;
            int h = c & 15;
            size_t off = ((size_t)(b*Hv + h))*Sv + s;
            if (c < 16) g_alpha[off] = 1.f / (1.f + expf(-(acc[i][j] + ab[h])));
            else        g_theta[off] = 0.01f / (1.f + expf(-(acc[i][j] + tb[h])));
        }
    }
}

// ---------------- per-bh reductions -----------------------------------------
__global__ void k_amean() {
    int bh = blockIdx.x; int tid = threadIdx.x;
    float s = 0.f;
    for (int i = tid; i < Sv; i += 256) s += g_alpha[(size_t)bh*Sv + i];
#pragma unroll
    for (int o = 16; o > 0; o >>= 1) s += __shfl_xor_sync(0xffffffffu, s, o);
    __shared__ float red[8];
    if ((tid & 31) == 0) red[tid >> 5] = s;
    __syncthreads();
    if (tid == 0) {
        float t = 0.f;
#pragma unroll
        for (int i = 0; i < 8; i++) t += red[i];
        g_amean[bh] = t / (float)Sv;
    }
}

__global__ void k_clip() {
    int bh = blockIdx.x; int tid = threadIdx.x;
    const float* a = g_g0 + (size_t)bh * 16384;
    const float* b = g_g1 + (size_t)bh * 16384;
    float s = 0.f;
    for (int i = tid; i < 16384; i += 256) {
        float v = a[i]; s += v*v;
        v = b[i]; s += v*v;
    }
#pragma unroll
    for (int o = 16; o > 0; o >>= 1) s += __shfl_xor_sync(0xffffffffu, s, o);
    __shared__ float red[8];
    if ((tid & 31) == 0) red[tid >> 5] = s;
    __syncthreads();
    if (tid == 0) {
        float t = 0.f;
#pragma unroll
        for (int i = 0; i < 8; i++) t += red[i];
        float c = 10.f / (sqrtf(t) + 1e-6f);
        g_coef[bh] = c < 1.f ? c : 1.f;
    }
}

// ---------------- fast-weight update ----------------------------------------
__global__ void k_neww(const float* __restrict__ Wsrc, const float* __restrict__ g,
                       float* __restrict__ out) {
    size_t idx = (size_t)blockIdx.x * 256 + threadIdx.x;  // 128*16384 total
    int bh = (int)(idx >> 14); int e = (int)(idx & 16383);
    float w = Wsrc[e];
    float nw = (1.f - g_amean[bh]) * w - g_coef[bh] * g[idx];
    out[idx] = isfinite(nw) ? nw : w;
}

// ---------------- retrieve epilogue: nan_to_num + pf_rmsnorm + residual -----
__global__ void k_final(float* __restrict__ out) {
    int r = blockIdx.x * 8 + (threadIdx.x >> 5);
    int lane = threadIdx.x & 31;
    size_t base = (size_t)r * 64;
    float h0 = g_pre1[base + lane], h1 = g_pre1[base + lane + 32];
    if (!isfinite(h0)) h0 = 0.f;
    if (!isfinite(h1)) h1 = 0.f;
    float ss = h0*h0 + h1*h1;
#pragma unroll
    for (int o = 16; o > 0; o >>= 1) ss += __shfl_xor_sync(0xffffffffu, ss, o);
    float rms = sqrtf(ss / 64.f + 1e-8f);
    float o0 = h0 / rms + g_q[base + lane];
    float o1 = h1 / rms + g_q[base + lane + 32];
    int bh = r >> 11, s = r & 2047;
    int b = bh >> 4, hh = bh & 15;
    size_t ob = ((size_t)(b*Sv + s))*Dv + hh*64;
    out[ob + lane]      = o0;
    out[ob + lane + 32] = o1;
}

// ============================================================================
extern "C" void kernel_launch(void* const* d_in, const int* in_sizes, int n_in,
                              void* d_out, int out_size) {
    (void)in_sizes; (void)n_in; (void)out_size;
    const float* x   = (const float*)d_in[0];
    const float* W_K = (const float*)d_in[1];
    const float* W_V = (const float*)d_in[2];
    const float* W_Q = (const float*)d_in[3];
    const float* mW0 = (const float*)d_in[4];
    const float* mW1 = (const float*)d_in[5];
    const float* knw = (const float*)d_in[6];
    const float* qnw = (const float*)d_in[7];
    const float* snw = (const float*)d_in[8];
    const float* rnw = (const float*)d_in[9];
    const float* aw  = (const float*)d_in[10];
    const float* ab  = (const float*)d_in[11];
    const float* tw  = (const float*)d_in[12];
    const float* tb  = (const float*)d_in[13];
    // eta (d_in[14], d_in[15]) provably does not affect the output (momentum=0)
    float* out = (float*)d_out;

    float *xn, *keys, *values, *q, *pre0, *h1, *dh, *pre1, *g0p, *g1p, *nW0, *nW1;
    cudaGetSymbolAddress((void**)&xn,     g_xn);
    cudaGetSymbolAddress((void**)&keys,   g_keys);
    cudaGetSymbolAddress((void**)&values, g_values);
    cudaGetSymbolAddress((void**)&q,      g_q);
    cudaGetSymbolAddress((void**)&pre0,   g_pre0);
    cudaGetSymbolAddress((void**)&h1,     g_h1);
    cudaGetSymbolAddress((void**)&dh,     g_dh);
    cudaGetSymbolAddress((void**)&pre1,   g_pre1);
    cudaGetSymbolAddress((void**)&g0p,    g_g0);
    cudaGetSymbolAddress((void**)&g1p,    g_g1);
    cudaGetSymbolAddress((void**)&nW0,    g_nW0);
    cudaGetSymbolAddress((void**)&nW1,    g_nW1);

    dim3 gb(8, 128);         // big GEMM: N/128 x M/128
    dim3 gk64(4, 2048);      // K=64 GEMM: N/64 x M/128

    // ---- store path ----
    k_rmsnorm_row<<<Mv, 256>>>(x, snw, xn);
    k_sgemm_splithead<<<gb, 256>>>(xn, W_K, keys);
    k_sgemm_splithead<<<gb, 256>>>(xn, W_V, values);
    k_rmsnorm64<<<MTv/8, 256>>>(keys, knw);
    k_gates<<<Mv/128, 256>>>(aw, ab, tw, tb);
    k_amean<<<BHv, 256>>>();

    k_gemm_k64<0><<<gk64, 256>>>(keys, mW0, 0, pre0, h1);
    k_gemm_k256<<<MTv/128, 256>>>(h1, mW1, 0, pre1);
    k_dh<<<MTv/8, 256>>>();
    // dh0 written in place over pre0 (same-thread same-offset read/write)
    k_gemm_k64<1><<<gk64, 256>>>(dh, mW1, 0, pre0, pre0);

    k_gradT<HIDv, HDv><<<dim3(1, 4, BHv), 256>>>(h1, dh, g1p);
    k_gradT<HDv, HIDv><<<dim3(4, 1, BHv), 256>>>(keys, pre0, g0p);
    k_clip<<<BHv, 256>>>();
    k_neww<<<(BHv*HDv*HIDv)/256, 256>>>(mW0, g0p, nW0);
    k_neww<<<(BHv*HIDv*HDv)/256, 256>>>(mW1, g1p, nW1);

    // ---- retrieve path ----
    k_rmsnorm_row<<<Mv, 256>>>(x, rnw, xn);
    k_sgemm_splithead<<<gb, 256>>>(xn, W_Q, q);
    k_rmsnorm64<<<MTv/8, 256>>>(q, qnw);
    k_gemm_k64<0><<<gk64, 256>>>(q, nW0, (long long)HDv*HIDv, nullptr, h1);
    k_gemm_k256<<<MTv/128, 256>>>(h1, nW1, (long long)HIDv*HDv, pre1);
    k_final<<<MTv/8, 256>>>(out);
}

// round 4
// speedup vs baseline: 1.5052x; 1.5052x over previous
#include <cuda_runtime.h>
#include <cuda_bf16.h>
#include <math.h>
#include <stdint.h>

// Problem constants
#define Bv   8
#define Sv   2048
#define Dv   1024
#define Hv   16
#define HDv  64
#define HIDv 256
#define BHv  128               // B*H
#define Mv   (Bv*Sv)           // 16384 rows of x
#define MTv  (BHv*Sv)          // 262144 rows per-head

// ------------------------- scratch (device globals) -------------------------
__device__ __nv_bfloat16 g_xnhi[Mv*Dv];   // 32 MB
__device__ __nv_bfloat16 g_xnlo[Mv*Dv];   // 32 MB
__device__ __nv_bfloat16 g_wthi[Dv*Dv];   // 2 MB (transposed weight, hi)
__device__ __nv_bfloat16 g_wtlo[Dv*Dv];   // 2 MB
__device__ float g_keys[MTv*HDv];      // 64 MB  (split-head)
__device__ float g_values[MTv*HDv];    // 64 MB
__device__ float g_q[MTv*HDv];         // 64 MB
__device__ float g_pre0[MTv*HIDv];     // 256 MB (pre-act, then dh0 in place)
__device__ float g_h1[MTv*HIDv];       // 256 MB (gelu act; reused in retrieve)
__device__ float g_pre1[MTv*HDv];      // 64 MB (reused in retrieve)
__device__ float g_dh[MTv*HDv];        // 64 MB
__device__ float g_alpha[BHv*Sv];
__device__ float g_theta[BHv*Sv];
__device__ float g_amean[BHv];
__device__ float g_coef[BHv];
__device__ float g_g0[BHv*HDv*HIDv];   // 8 MB
__device__ float g_g1[BHv*HIDv*HDv];   // 8 MB
__device__ float g_nW0[BHv*HDv*HIDv];
__device__ float g_nW1[BHv*HIDv*HDv];

// ========================= mma.sync helpers =================================
__device__ __forceinline__ uint32_t smem_u32(const void* p) {
    uint32_t a;
    asm("{ .reg .u64 t; cvta.to.shared.u64 t, %1; cvt.u32.u64 %0, t; }"
        : "=r"(a) : "l"(p));
    return a;
}

__device__ __forceinline__ void ldsm4(uint32_t* d, uint32_t addr) {
    asm volatile("ldmatrix.sync.aligned.m8n8.x4.shared.b16 {%0,%1,%2,%3}, [%4];"
                 : "=r"(d[0]), "=r"(d[1]), "=r"(d[2]), "=r"(d[3]) : "r"(addr));
}

__device__ __forceinline__ void mma16816(float* c, const uint32_t* a, const uint32_t* b) {
    asm volatile("mma.sync.aligned.m16n8k16.row.col.f32.bf16.bf16.f32 "
                 "{%0,%1,%2,%3}, {%4,%5,%6,%7}, {%8,%9}, {%0,%1,%2,%3};"
                 : "+f"(c[0]), "+f"(c[1]), "+f"(c[2]), "+f"(c[3])
                 : "r"(a[0]), "r"(a[1]), "r"(a[2]), "r"(a[3]), "r"(b[0]), "r"(b[1]));
}

__device__ __forceinline__ void cp16(uint32_t dst, const void* src) {
    asm volatile("cp.async.cg.shared.global [%0], [%1], 16;" :: "r"(dst), "l"(src) : "memory");
}

// ---------------- rmsnorm over D=1024 rows, emit bf16 hi/lo -----------------
__global__ void k_rmsnorm_split(const float* __restrict__ x, const float* __restrict__ w,
                                __nv_bfloat16* __restrict__ hi, __nv_bfloat16* __restrict__ lo) {
    int row = blockIdx.x;
    const float* xr = x + (size_t)row * Dv;
    int tid = threadIdx.x;  // 256
    float v[4]; float ss = 0.f;
#pragma unroll
    for (int i = 0; i < 4; i++) { v[i] = xr[tid + i*256]; ss += v[i]*v[i]; }
#pragma unroll
    for (int o = 16; o > 0; o >>= 1) ss += __shfl_xor_sync(0xffffffffu, ss, o);
    __shared__ float red[8];
    __shared__ float rinv;
    if ((tid & 31) == 0) red[tid >> 5] = ss;
    __syncthreads();
    if (tid == 0) {
        float t = 0.f;
#pragma unroll
        for (int i = 0; i < 8; i++) t += red[i];
        rinv = rsqrtf(t / (float)Dv + 1e-6f);
    }
    __syncthreads();
    float r = rinv;
#pragma unroll
    for (int i = 0; i < 4; i++) {
        float val = v[i] * w[tid + i*256] * r;
        __nv_bfloat16 h = __float2bfloat16(val);
        hi[(size_t)row*Dv + tid + i*256] = h;
        lo[(size_t)row*Dv + tid + i*256] = __float2bfloat16(val - __bfloat162float(h));
    }
}

// ---------------- transpose + bf16-split weight (1024x1024) ----------------
__global__ void k_wsplit(const float* __restrict__ W,
                         __nv_bfloat16* __restrict__ Thi, __nv_bfloat16* __restrict__ Tlo) {
    __shared__ float t[32][33];
    int k0 = blockIdx.y * 32, n0 = blockIdx.x * 32;
    int tx = threadIdx.x, ty = threadIdx.y;   // (32, 8)
#pragma unroll
    for (int r = 0; r < 4; r++)
        t[ty + r*8][tx] = W[(size_t)(k0 + ty + r*8)*Dv + n0 + tx];
    __syncthreads();
#pragma unroll
    for (int r = 0; r < 4; r++) {
        float v = t[tx][ty + r*8];
        __nv_bfloat16 h = __float2bfloat16(v);
        size_t off = (size_t)(n0 + ty + r*8)*Dv + k0 + tx;
        Thi[off] = h;
        Tlo[off] = __float2bfloat16(v - __bfloat162float(h));
    }
}

// -------- mma.sync GEMM: (16384x1024)@(1024x1024), split-head out -----------
// A = xn (bf16 hi/lo, row-major [m][k]); B = W^T (bf16 hi/lo, [n][k]).
// C[m][n] = sum_k A[m][k]*W[k][n]; fp32 accum; bf16 3-term split product.
// SMEM per stage: 4 layers (Ahi, Alo, Bhi, Blo) of [128][64]bf16 = 16KB each.
#define MMA_SMEM (2*65536)
__global__ void __launch_bounds__(256)
k_gemm_mma(const __nv_bfloat16* __restrict__ Ahi, const __nv_bfloat16* __restrict__ Alo,
           const __nv_bfloat16* __restrict__ Bhi, const __nv_bfloat16* __restrict__ Blo,
           float* __restrict__ C) {
    extern __shared__ char smem[];
    uint32_t sb = smem_u32(smem);
    int tid = threadIdx.x;
    int wid = tid >> 5, lane = tid & 31;
    int wm = wid >> 1, wn = wid & 1;          // warps 4(M) x 2(N)
    int m0 = blockIdx.y * 128, n0 = blockIdx.x * 128;

    const __nv_bfloat16* base_l[4] = {
        Ahi + (size_t)m0 * Dv, Alo + (size_t)m0 * Dv,
        Bhi + (size_t)n0 * Dv, Blo + (size_t)n0 * Dv };

#define LOAD_STAGE(CH, ST) do {                                                \
    int _k0 = (CH) * 64;                                                       \
    uint32_t _sb = sb + (ST) * 65536;                                          \
    _Pragma("unroll")                                                          \
    for (int i = 0; i < 16; i++) {                                             \
        int idx = i * 256 + tid;                                               \
        int layer = idx >> 10, rem = idx & 1023;                               \
        int r = rem >> 3, c16 = rem & 7;                                       \
        const __nv_bfloat16* src = base_l[layer] + (size_t)r * Dv + _k0 + c16 * 8; \
        uint32_t dst = _sb + layer * 16384 + r * 128 + (((c16 ^ (r & 7))) << 4); \
        cp16(dst, src);                                                        \
    }                                                                          \
    asm volatile("cp.async.commit_group;" ::: "memory");                       \
} while (0)

    LOAD_STAGE(0, 0);

    float acc[2][8][4];
#pragma unroll
    for (int mt = 0; mt < 2; mt++)
#pragma unroll
        for (int nt = 0; nt < 8; nt++)
#pragma unroll
            for (int e = 0; e < 4; e++) acc[mt][nt][e] = 0.f;

    for (int ch = 0; ch < 16; ch++) {
        if (ch < 15) {
            LOAD_STAGE(ch + 1, (ch + 1) & 1);
            asm volatile("cp.async.wait_group 1;" ::: "memory");
        } else {
            asm volatile("cp.async.wait_group 0;" ::: "memory");
        }
        __syncthreads();

        uint32_t sA = sb + (ch & 1) * 65536;       // +0 hi, +16384 lo
        uint32_t sB = sA + 32768;                  // +0 hi, +16384 lo
#pragma unroll
        for (int kk = 0; kk < 4; kk++) {
            uint32_t a_hi[2][4], a_lo[2][4];
#pragma unroll
            for (int mt = 0; mt < 2; mt++) {
                int r = wm*32 + mt*16 + (lane & 7) + ((lane >> 3) & 1) * 8;
                int cch = kk*2 + (lane >> 4);
                uint32_t off = r * 128 + (((cch ^ (r & 7))) << 4);
                ldsm4(a_hi[mt], sA + off);
                ldsm4(a_lo[mt], sA + 16384 + off);
            }
            uint32_t b_hi[8][2], b_lo[8][2];
#pragma unroll
            for (int np = 0; np < 4; np++) {
                int r = wn*64 + np*16 + (lane & 7) + ((lane >> 4) & 1) * 8;
                int cch = kk*2 + ((lane >> 3) & 1);
                uint32_t off = r * 128 + (((cch ^ (r & 7))) << 4);
                uint32_t d[4];
                ldsm4(d, sB + off);
                b_hi[2*np][0] = d[0]; b_hi[2*np][1] = d[1];
                b_hi[2*np+1][0] = d[2]; b_hi[2*np+1][1] = d[3];
                ldsm4(d, sB + 16384 + off);
                b_lo[2*np][0] = d[0]; b_lo[2*np][1] = d[1];
                b_lo[2*np+1][0] = d[2]; b_lo[2*np+1][1] = d[3];
            }
#pragma unroll
            for (int mt = 0; mt < 2; mt++)
#pragma unroll
                for (int nt = 0; nt < 8; nt++) {
                    mma16816(acc[mt][nt], a_hi[mt], b_hi[nt]);
                    mma16816(acc[mt][nt], a_hi[mt], b_lo[nt]);
                    mma16816(acc[mt][nt], a_lo[mt], b_hi[nt]);
                }
        }
        __syncthreads();
    }

    // epilogue: split-head store. CTA spans one batch b (128 | 2048).
    int b = m0 >> 11;
#pragma unroll
    for (int mt = 0; mt < 2; mt++) {
        int mrow = m0 + wm*32 + mt*16 + (lane >> 2);
        int s = mrow & 2047;
#pragma unroll
        for (int nt = 0; nt < 8; nt++) {
            int col = n0 + wn*64 + nt*8 + (lane & 3) * 2;
            int h = col >> 6, hd = col & 63;
            size_t ob = (((size_t)(b*Hv + h))*Sv) * 64 + (size_t)hd;
            *(float2*)&C[ob + (size_t)s*64]       = make_float2(acc[mt][nt][0], acc[mt][nt][1]);
            *(float2*)&C[ob + (size_t)(s + 8)*64] = make_float2(acc[mt][nt][2], acc[mt][nt][3]);
        }
    }
#undef LOAD_STAGE
}

// ------------------------- rmsnorm over 64-wide rows, in place --------------
__global__ void k_rmsnorm64(float* __restrict__ x, const float* __restrict__ w) {
    int r = blockIdx.x * 8 + (threadIdx.x >> 5);
    int lane = threadIdx.x & 31;
    float* xr = x + (size_t)r * 64;
    float a = xr[lane], b = xr[lane + 32];
    float ss = a*a + b*b;
#pragma unroll
    for (int o = 16; o > 0; o >>= 1) ss += __shfl_xor_sync(0xffffffffu, ss, o);
    float rr = rsqrtf(ss / 64.f + 1e-6f);
    xr[lane]      = a * w[lane]      * rr;
    xr[lane + 32] = b * w[lane + 32] * rr;
}

// -------- K=64 GEMM: (MT x 64) @ (64 x 256), optional batched weight --------
template <int MODE>
__global__ void __launch_bounds__(256)
k_gemm_k64(const float* __restrict__ A, const float* __restrict__ W,
           long long wstride, float* __restrict__ out1, float* __restrict__ out2) {
    __shared__ float As[64][128];
    __shared__ float Bs[64][64];
    int bm = blockIdx.y, bn = blockIdx.x;
    int tid = threadIdx.x;
    int m0 = bm * 128, n0 = bn * 64;
    int bh = m0 >> 11;
    const float* Wp = W + (size_t)bh * wstride;
#pragma unroll
    for (int i = 0; i < 8; i++) {
        int idx = tid + i*256;
        int r = idx >> 4, c4 = idx & 15;
        float4 v = *(const float4*)(A + (size_t)(m0 + r)*64 + c4*4);
        As[c4*4+0][r] = v.x; As[c4*4+1][r] = v.y;
        As[c4*4+2][r] = v.z; As[c4*4+3][r] = v.w;
    }
    if (MODE == 0) {
#pragma unroll
        for (int i = 0; i < 4; i++) {
            int idx = tid + i*256;
            int r = idx >> 4, c4 = idx & 15;
            *(float4*)&Bs[r][c4*4] = *(const float4*)(Wp + (size_t)r*256 + n0 + c4*4);
        }
    } else {
#pragma unroll
        for (int i = 0; i < 4; i++) {
            int idx = tid + i*256;
            int n = idx >> 4, c4 = idx & 15;
            float4 v = *(const float4*)(Wp + (size_t)(n0 + n)*64 + c4*4);
            Bs[c4*4+0][n] = v.x; Bs[c4*4+1][n] = v.y;
            Bs[c4*4+2][n] = v.z; Bs[c4*4+3][n] = v.w;
        }
    }
    __syncthreads();
    int ty = tid >> 4, tx = tid & 15;
    float acc[8][4] = {};
#pragma unroll
    for (int k = 0; k < 64; k++) {
        float ra[8], rb[4];
#pragma unroll
        for (int i = 0; i < 8; i++) ra[i] = As[k][ty*8 + i];
#pragma unroll
        for (int j = 0; j < 4; j++) rb[j] = Bs[k][tx*4 + j];
#pragma unroll
        for (int i = 0; i < 8; i++)
#pragma unroll
            for (int j = 0; j < 4; j++) acc[i][j] += ra[i] * rb[j];
    }
#pragma unroll
    for (int i = 0; i < 8; i++) {
        size_t m = (size_t)m0 + ty*8 + i;
#pragma unroll
        for (int j = 0; j < 4; j++) {
            int n = n0 + tx*4 + j;
            size_t off = m*256 + n;
            float v = acc[i][j];
            if (MODE == 0) {
                if (out1) out1[off] = v;
                out2[off] = 0.5f * v * (1.f + erff(v * 0.70710678118654752f));
            } else {
                float p = out2[off];
                float cdf = 0.5f * (1.f + erff(p * 0.70710678118654752f));
                float pdf = expf(-0.5f * p * p) * 0.3989422804014327f;
                out1[off] = v * (cdf + p * pdf);
            }
        }
    }
}

// -------- K=256 GEMM: (MT x 256) @ (256 x 64), optional batched weight ------
__global__ void __launch_bounds__(256)
k_gemm_k256(const float* __restrict__ A, const float* __restrict__ W,
            long long wstride, float* __restrict__ C) {
    __shared__ float As[32][128];
    __shared__ float Bs[32][64];
    int bm = blockIdx.x;
    int tid = threadIdx.x;
    int m0 = bm * 128;
    int bh = m0 >> 11;
    const float* Wp = W + (size_t)bh * wstride;
    int ty = tid >> 4, tx = tid & 15;
    float acc[8][4] = {};
    for (int k0 = 0; k0 < 256; k0 += 32) {
#pragma unroll
        for (int i = 0; i < 4; i++) {
            int idx = tid + i*256;
            int r = idx >> 3, c4 = idx & 7;
            float4 v = *(const float4*)(A + (size_t)(m0 + r)*256 + k0 + c4*4);
            As[c4*4+0][r] = v.x; As[c4*4+1][r] = v.y;
            As[c4*4+2][r] = v.z; As[c4*4+3][r] = v.w;
        }
#pragma unroll
        for (int i = 0; i < 2; i++) {
            int idx = tid + i*256;
            int r = idx >> 4, c4 = idx & 15;
            *(float4*)&Bs[r][c4*4] = *(const float4*)(Wp + (size_t)(k0 + r)*64 + c4*4);
        }
        __syncthreads();
#pragma unroll
        for (int k = 0; k < 32; k++) {
            float ra[8], rb[4];
#pragma unroll
            for (int i = 0; i < 8; i++) ra[i] = As[k][ty*8 + i];
#pragma unroll
            for (int j = 0; j < 4; j++) rb[j] = Bs[k][tx*4 + j];
#pragma unroll
            for (int i = 0; i < 8; i++)
#pragma unroll
                for (int j = 0; j < 4; j++) acc[i][j] += ra[i] * rb[j];
        }
        __syncthreads();
    }
#pragma unroll
    for (int i = 0; i < 8; i++) {
        size_t m = (size_t)m0 + ty*8 + i;
#pragma unroll
        for (int j = 0; j < 4; j++) C[m*64 + tx*4 + j] = acc[i][j];
    }
}

// ---------- fused pf_rmsnorm fwd+bwd for the store loss gradient ------------
__global__ void k_dh() {
    int r = blockIdx.x * 8 + (threadIdx.x >> 5);
    int lane = threadIdx.x & 31;
    size_t base = (size_t)r * 64;
    float h0 = g_pre1[base + lane], h1 = g_pre1[base + lane + 32];
    float ss = h0*h0 + h1*h1;
#pragma unroll
    for (int o = 16; o > 0; o >>= 1) ss += __shfl_xor_sync(0xffffffffu, ss, o);
    float rms = sqrtf(ss / 64.f + 1e-8f);
    float hn0 = h0 / rms, hn1 = h1 / rms;
    float t = g_theta[r];
    float dp0 = 2.f * t * ((hn0 + g_keys[base + lane])      - g_values[base + lane]);
    float dp1 = 2.f * t * ((hn1 + g_keys[base + lane + 32]) - g_values[base + lane + 32]);
    float dy = dp0*hn0 + dp1*hn1;
#pragma unroll
    for (int o = 16; o > 0; o >>= 1) dy += __shfl_xor_sync(0xffffffffu, dy, o);
    g_dh[base + lane]      = (dp0 - hn0 * dy / 64.f) / rms;
    g_dh[base + lane + 32] = (dp1 - hn1 * dy / 64.f) / rms;
}

// ---------------- batched A^T B weight-gradient GEMM ------------------------
template <int I, int O>
__global__ void __launch_bounds__(256)
k_gradT(const float* __restrict__ A, const float* __restrict__ Bm,
        float* __restrict__ G) {
    __shared__ float At[32][64];
    __shared__ float Bt[32][64];
    int bh = blockIdx.z;
    int i0 = blockIdx.y * 64, o0 = blockIdx.x * 64;
    int tid = threadIdx.x;
    int ty = tid >> 4, tx = tid & 15;
    float acc[4][4] = {};
    const float* Ab = A  + (size_t)bh * Sv * I;
    const float* Bb = Bm + (size_t)bh * Sv * O;
    for (int s0 = 0; s0 < Sv; s0 += 32) {
#pragma unroll
        for (int i = 0; i < 2; i++) {
            int idx = tid + i*256;
            int r = idx >> 4, c4 = idx & 15;
            *(float4*)&At[r][c4*4] = *(const float4*)(Ab + (size_t)(s0 + r)*I + i0 + c4*4);
            *(float4*)&Bt[r][c4*4] = *(const float4*)(Bb + (size_t)(s0 + r)*O + o0 + c4*4);
        }
        __syncthreads();
#pragma unroll
        for (int k = 0; k < 32; k++) {
            float ra[4], rb[4];
#pragma unroll
            for (int i = 0; i < 4; i++) ra[i] = At[k][ty*4 + i];
#pragma unroll
            for (int j = 0; j < 4; j++) rb[j] = Bt[k][tx*4 + j];
#pragma unroll
            for (int i = 0; i < 4; i++)
#pragma unroll
                for (int j = 0; j < 4; j++) acc[i][j] += ra[i] * rb[j];
        }
        __syncthreads();
    }
#pragma unroll
    for (int i = 0; i < 4; i++)
#pragma unroll
        for (int j = 0; j < 4; j++)
            G[((size_t)bh*I + i0 + ty*4 + i)*O + o0 + tx*4 + j] = acc[i][j];
}

// ---------------- gates: alpha, theta (sigmoid) in (BH, S) layout -----------
__global__ void __launch_bounds__(256)
k_gates(const float* __restrict__ aw, const float* __restrict__ ab,
        const float* __restrict__ tw, const float* __restrict__ tb) {
    __shared__ float Xs[64][128];
    __shared__ float Ws[64][32];
    int m0 = blockIdx.x * 128;
    int tid = threadIdx.x;
    int rg = tid >> 3, cg = tid & 7;
    float acc[4][4] = {};
    for (int k0 = 0; k0 < 1024; k0 += 64) {
#pragma unroll
        for (int i = 0; i < 4; i++) {
            int idx = tid + i*256;            // 0..1023
            int r = idx >> 3, c8 = idx & 7;
            size_t ga = (size_t)(m0 + r)*1024 + k0 + c8*8;
            uint4 vh = *(const uint4*)&g_xnhi[ga];
            uint4 vl = *(const uint4*)&g_xnlo[ga];
            __nv_bfloat162 h2[4], l2[4];
            *(uint4*)h2 = vh; *(uint4*)l2 = vl;
#pragma unroll
            for (int j = 0; j < 4; j++) {
                float2 fh = __bfloat1622float2(h2[j]);
                float2 fl = __bfloat1622float2(l2[j]);
                Xs[c8*8 + 2*j][r]     = fh.x + fl.x;
                Xs[c8*8 + 2*j + 1][r] = fh.y + fl.y;
            }
        }
#pragma unroll
        for (int i = 0; i < 2; i++) {
            int idx = tid + i*256;
            int r = idx >> 3, c4 = idx & 7;
            const float* src = (c4 < 4) ? (aw + (size_t)(k0 + r)*16 + c4*4)
                                        : (tw + (size_t)(k0 + r)*16 + (c4 - 4)*4);
            *(float4*)&Ws[r][c4*4] = *(const float4*)src;
        }
        __syncthreads();
#pragma unroll
        for (int k = 0; k < 64; k++) {
            float ra[4], rb[4];
#pragma unroll
            for (int i = 0; i < 4; i++) ra[i] = Xs[k][rg*4 + i];
#pragma unroll
            for (int j = 0; j < 4; j++) rb[j] = Ws[k][cg*4 + j];
#pragma unroll
            for (int i = 0; i < 4; i++)
#pragma unroll
                for (int j = 0; j < 4; j++) acc[i][j] += ra[i] * rb[j];
        }
        __syncthreads();
    }
#pragma unroll
    for (int i = 0; i < 4; i++) {
        int m = m0 + rg*4 + i;
        int b = m >> 11, s = m & 2047;
#pragma unroll
        for (int j = 0; j < 4; j++) {
            int c = cg*4 + j;
            int h = c & 15;
            size_t off = ((size_t)(b*Hv + h))*Sv + s;
            if (c < 16) g_alpha[off] = 1.f / (1.f + expf(-(acc[i][j] + ab[h])));
            else        g_theta[off] = 0.01f / (1.f + expf(-(acc[i][j] + tb[h])));
        }
    }
}

// ---------------- per-bh reductions -----------------------------------------
__global__ void k_amean() {
    int bh = blockIdx.x; int tid = threadIdx.x;
    float s = 0.f;
    for (int i = tid; i < Sv; i += 256) s += g_alpha[(size_t)bh*Sv + i];
#pragma unroll
    for (int o = 16; o > 0; o >>= 1) s += __shfl_xor_sync(0xffffffffu, s, o);
    __shared__ float red[8];
    if ((tid & 31) == 0) red[tid >> 5] = s;
    __syncthreads();
    if (tid == 0) {
        float t = 0.f;
#pragma unroll
        for (int i = 0; i < 8; i++) t += red[i];
        g_amean[bh] = t / (float)Sv;
    }
}

__global__ void k_clip() {
    int bh = blockIdx.x; int tid = threadIdx.x;
    const float* a = g_g0 + (size_t)bh * 16384;
    const float* b = g_g1 + (size_t)bh * 16384;
    float s = 0.f;
    for (int i = tid; i < 16384; i += 256) {
        float v = a[i]; s += v*v;
        v = b[i]; s += v*v;
    }
#pragma unroll
    for (int o = 16; o > 0; o >>= 1) s += __shfl_xor_sync(0xffffffffu, s, o);
    __shared__ float red[8];
    if ((tid & 31) == 0) red[tid >> 5] = s;
    __syncthreads();
    if (tid == 0) {
        float t = 0.f;
#pragma unroll
        for (int i = 0; i < 8; i++) t += red[i];
        float c = 10.f / (sqrtf(t) + 1e-6f);
        g_coef[bh] = c < 1.f ? c : 1.f;
    }
}

// ---------------- fast-weight update ----------------------------------------
__global__ void k_neww(const float* __restrict__ Wsrc, const float* __restrict__ g,
                       float* __restrict__ out) {
    size_t idx = (size_t)blockIdx.x * 256 + threadIdx.x;
    int bh = (int)(idx >> 14); int e = (int)(idx & 16383);
    float w = Wsrc[e];
    float nw = (1.f - g_amean[bh]) * w - g_coef[bh] * g[idx];
    out[idx] = isfinite(nw) ? nw : w;
}

// ---------------- retrieve epilogue: nan_to_num + pf_rmsnorm + residual -----
__global__ void k_final(float* __restrict__ out) {
    int r = blockIdx.x * 8 + (threadIdx.x >> 5);
    int lane = threadIdx.x & 31;
    size_t base = (size_t)r * 64;
    float h0 = g_pre1[base + lane], h1 = g_pre1[base + lane + 32];
    if (!isfinite(h0)) h0 = 0.f;
    if (!isfinite(h1)) h1 = 0.f;
    float ss = h0*h0 + h1*h1;
#pragma unroll
    for (int o = 16; o > 0; o >>= 1) ss += __shfl_xor_sync(0xffffffffu, ss, o);
    float rms = sqrtf(ss / 64.f + 1e-8f);
    float o0 = h0 / rms + g_q[base + lane];
    float o1 = h1 / rms + g_q[base + lane + 32];
    int bh = r >> 11, s = r & 2047;
    int b = bh >> 4, hh = bh & 15;
    size_t ob = ((size_t)(b*Sv + s))*Dv + hh*64;
    out[ob + lane]      = o0;
    out[ob + lane + 32] = o1;
}

// ============================================================================
extern "C" void kernel_launch(void* const* d_in, const int* in_sizes, int n_in,
                              void* d_out, int out_size) {
    (void)in_sizes; (void)n_in; (void)out_size;
    const float* x   = (const float*)d_in[0];
    const float* W_K = (const float*)d_in[1];
    const float* W_V = (const float*)d_in[2];
    const float* W_Q = (const float*)d_in[3];
    const float* mW0 = (const float*)d_in[4];
    const float* mW1 = (const float*)d_in[5];
    const float* knw = (const float*)d_in[6];
    const float* qnw = (const float*)d_in[7];
    const float* snw = (const float*)d_in[8];
    const float* rnw = (const float*)d_in[9];
    const float* aw  = (const float*)d_in[10];
    const float* ab  = (const float*)d_in[11];
    const float* tw  = (const float*)d_in[12];
    const float* tb  = (const float*)d_in[13];
    // eta (d_in[14], d_in[15]) provably does not affect the output (momentum=0)
    float* out = (float*)d_out;

    __nv_bfloat16 *xnhi, *xnlo, *wthi, *wtlo;
    float *keys, *values, *q, *pre0, *h1, *dh, *pre1, *g0p, *g1p, *nW0, *nW1;
    cudaGetSymbolAddress((void**)&xnhi,   g_xnhi);
    cudaGetSymbolAddress((void**)&xnlo,   g_xnlo);
    cudaGetSymbolAddress((void**)&wthi,   g_wthi);
    cudaGetSymbolAddress((void**)&wtlo,   g_wtlo);
    cudaGetSymbolAddress((void**)&keys,   g_keys);
    cudaGetSymbolAddress((void**)&values, g_values);
    cudaGetSymbolAddress((void**)&q,      g_q);
    cudaGetSymbolAddress((void**)&pre0,   g_pre0);
    cudaGetSymbolAddress((void**)&h1,     g_h1);
    cudaGetSymbolAddress((void**)&dh,     g_dh);
    cudaGetSymbolAddress((void**)&pre1,   g_pre1);
    cudaGetSymbolAddress((void**)&g0p,    g_g0);
    cudaGetSymbolAddress((void**)&g1p,    g_g1);
    cudaGetSymbolAddress((void**)&nW0,    g_nW0);
    cudaGetSymbolAddress((void**)&nW1,    g_nW1);

    cudaFuncSetAttribute(k_gemm_mma, cudaFuncAttributeMaxDynamicSharedMemorySize, MMA_SMEM);

    dim3 gtc(8, 128);        // mma GEMM: N/128 x M/128
    dim3 gws(32, 32);        // weight split
    dim3 bws(32, 8);
    dim3 gk64(4, 2048);      // K=64 GEMM: N/64 x M/128

    // ---- store path ----
    k_rmsnorm_split<<<Mv, 256>>>(x, snw, xnhi, xnlo);
    k_wsplit<<<gws, bws>>>(W_K, wthi, wtlo);
    k_gemm_mma<<<gtc, 256, MMA_SMEM>>>(xnhi, xnlo, wthi, wtlo, keys);
    k_wsplit<<<gws, bws>>>(W_V, wthi, wtlo);
    k_gemm_mma<<<gtc, 256, MMA_SMEM>>>(xnhi, xnlo, wthi, wtlo, values);
    k_rmsnorm64<<<MTv/8, 256>>>(keys, knw);
    k_gates<<<Mv/128, 256>>>(aw, ab, tw, tb);
    k_amean<<<BHv, 256>>>();

    k_gemm_k64<0><<<gk64, 256>>>(keys, mW0, 0, pre0, h1);
    k_gemm_k256<<<MTv/128, 256>>>(h1, mW1, 0, pre1);
    k_dh<<<MTv/8, 256>>>();
    // dh0 written in place over pre0 (same-thread same-offset read/write)
    k_gemm_k64<1><<<gk64, 256>>>(dh, mW1, 0, pre0, pre0);

    k_gradT<HIDv, HDv><<<dim3(1, 4, BHv), 256>>>(h1, dh, g1p);
    k_gradT<HDv, HIDv><<<dim3(4, 1, BHv), 256>>>(keys, pre0, g0p);
    k_clip<<<BHv, 256>>>();
    k_neww<<<(BHv*HDv*HIDv)/256, 256>>>(mW0, g0p, nW0);
    k_neww<<<(BHv*HIDv*HDv)/256, 256>>>(mW1, g1p, nW1);

    // ---- retrieve path ----
    k_rmsnorm_split<<<Mv, 256>>>(x, rnw, xnhi, xnlo);
    k_wsplit<<<gws, bws>>>(W_Q, wthi, wtlo);
    k_gemm_mma<<<gtc, 256, MMA_SMEM>>>(xnhi, xnlo, wthi, wtlo, q);
    k_rmsnorm64<<<MTv/8, 256>>>(q, qnw);
    k_gemm_k64<0><<<gk64, 256>>>(q, nW0, (long long)HDv*HIDv, nullptr, h1);
    k_gemm_k256<<<MTv/128, 256>>>(h1, nW1, (long long)HIDv*HDv, pre1);
    k_final<<<MTv/8, 256>>>(out);
}

// round 6
// speedup vs baseline: 2.3054x; 1.5316x over previous
#include <cuda_runtime.h>
#include <cuda_bf16.h>
#include <cuda_fp16.h>
#include <math.h>
#include <stdint.h>

// Problem constants
#define Bv   8
#define Sv   2048
#define Dv   1024
#define Hv   16
#define HDv  64
#define HIDv 256
#define BHv  128               // B*H
#define Mv   (Bv*Sv)           // 16384 rows of x
#define MTv  (BHv*Sv)          // 262144 rows per-head

typedef __nv_bfloat16 bf16;
typedef __half f16;

// ------------------------- scratch (device globals) -------------------------
__device__ bf16 g_xnhi[Mv*Dv];        // 32 MB
__device__ bf16 g_xnlo[Mv*Dv];        // 32 MB
__device__ bf16 g_wthi[Dv*Dv];        // 2 MB
__device__ bf16 g_wtlo[Dv*Dv];        // 2 MB
__device__ float g_keys[MTv*HDv];     // 64 MB  (raw K proj, split-head)
__device__ float g_values[MTv*HDv];   // 64 MB
__device__ float g_q[MTv*HDv];        // 64 MB  (raw then normed in place)
__device__ float g_pre1[MTv*HDv];     // 64 MB
__device__ f16  g_keysb[MTv*HDv];     // 32 MB (normed keys, fp16)
__device__ bf16 g_qhi[MTv*HDv];       // 32 MB
__device__ bf16 g_qlo[MTv*HDv];       // 32 MB
__device__ f16  g_dhb[MTv*HDv];       // 32 MB
// pooled scratch: pre0h@0, h1h@128M, dh0h@256M; retrieve: h1rhi@0, h1rlo@256M
__device__ __align__(256) char g_pool[402653184];   // 384 MB
__device__ float g_alpha[BHv*Sv];
__device__ float g_theta[BHv*Sv];
__device__ float g_amean[BHv];
__device__ float g_coef[BHv];
__device__ float g_g0[BHv*HIDv*HDv];  // g0^T [bh][256][64] fp32
__device__ float g_g1[BHv*HDv*HIDv];  // g1^T [bh][64][256] fp32
__device__ float g_mW0T[HIDv*HDv];    __device__ f16 g_mW0Tb[HIDv*HDv];
__device__ float g_mW1T[HDv*HIDv];    __device__ f16 g_mW1Tb[HDv*HIDv];
__device__ f16 g_mW1b[HIDv*HDv];
__device__ bf16 g_nW0Thi[BHv*HIDv*HDv], g_nW0Tlo[BHv*HIDv*HDv];
__device__ bf16 g_nW1Thi[BHv*HDv*HIDv], g_nW1Tlo[BHv*HDv*HIDv];

// ========================= mma.sync helpers =================================
__device__ __forceinline__ uint32_t smem_u32(const void* p) {
    uint32_t a;
    asm("{ .reg .u64 t; cvta.to.shared.u64 t, %1; cvt.u32.u64 %0, t; }"
        : "=r"(a) : "l"(p));
    return a;
}
__device__ __forceinline__ void ldsm4(uint32_t* d, uint32_t addr) {
    asm volatile("ldmatrix.sync.aligned.m8n8.x4.shared.b16 {%0,%1,%2,%3}, [%4];"
                 : "=r"(d[0]), "=r"(d[1]), "=r"(d[2]), "=r"(d[3]) : "r"(addr));
}
__device__ __forceinline__ void ldsm4t(uint32_t* d, uint32_t addr) {
    asm volatile("ldmatrix.sync.aligned.m8n8.x4.trans.shared.b16 {%0,%1,%2,%3}, [%4];"
                 : "=r"(d[0]), "=r"(d[1]), "=r"(d[2]), "=r"(d[3]) : "r"(addr));
}
template <typename T> struct MmaOp;
template <> struct MmaOp<bf16> {
    static __device__ __forceinline__ void run(float* c, const uint32_t* a, const uint32_t* b) {
        asm volatile("mma.sync.aligned.m16n8k16.row.col.f32.bf16.bf16.f32 "
                     "{%0,%1,%2,%3}, {%4,%5,%6,%7}, {%8,%9}, {%0,%1,%2,%3};"
                     : "+f"(c[0]), "+f"(c[1]), "+f"(c[2]), "+f"(c[3])
                     : "r"(a[0]), "r"(a[1]), "r"(a[2]), "r"(a[3]), "r"(b[0]), "r"(b[1]));
    }
};
template <> struct MmaOp<f16> {
    static __device__ __forceinline__ void run(float* c, const uint32_t* a, const uint32_t* b) {
        asm volatile("mma.sync.aligned.m16n8k16.row.col.f32.f16.f16.f32 "
                     "{%0,%1,%2,%3}, {%4,%5,%6,%7}, {%8,%9}, {%0,%1,%2,%3};"
                     : "+f"(c[0]), "+f"(c[1]), "+f"(c[2]), "+f"(c[3])
                     : "r"(a[0]), "r"(a[1]), "r"(a[2]), "r"(a[3]), "r"(b[0]), "r"(b[1]));
    }
};
template <typename T> __device__ __forceinline__ T fromf(float v);
template <> __device__ __forceinline__ bf16 fromf<bf16>(float v) { return __float2bfloat16(v); }
template <> __device__ __forceinline__ f16  fromf<f16>(float v)  { return __float2half(v); }
__device__ __forceinline__ float tof(bf16 v) { return __bfloat162float(v); }
__device__ __forceinline__ float tof(f16 v)  { return __half2float(v); }

__device__ __forceinline__ void cp16(uint32_t dst, const void* src) {
    asm volatile("cp.async.cg.shared.global [%0], [%1], 16;" :: "r"(dst), "l"(src) : "memory");
}
__device__ __forceinline__ float geluf(float v) {
    return 0.5f * v * (1.f + erff(v * 0.70710678118654752f));
}
__device__ __forceinline__ float gelugrad(float p) {
    float cdf = 0.5f * (1.f + erff(p * 0.70710678118654752f));
    float pdf = expf(-0.5f * p * p) * 0.3989422804014327f;
    return cdf + p * pdf;
}

// ---------------- rmsnorm over D=1024 rows, emit bf16 hi/lo -----------------
__global__ void k_rmsnorm_split(const float* __restrict__ x, const float* __restrict__ w,
                                bf16* __restrict__ hi, bf16* __restrict__ lo) {
    int row = blockIdx.x;
    const float* xr = x + (size_t)row * Dv;
    int tid = threadIdx.x;  // 256
    float v[4]; float ss = 0.f;
#pragma unroll
    for (int i = 0; i < 4; i++) { v[i] = xr[tid + i*256]; ss += v[i]*v[i]; }
#pragma unroll
    for (int o = 16; o > 0; o >>= 1) ss += __shfl_xor_sync(0xffffffffu, ss, o);
    __shared__ float red[8];
    __shared__ float rinv;
    if ((tid & 31) == 0) red[tid >> 5] = ss;
    __syncthreads();
    if (tid == 0) {
        float t = 0.f;
#pragma unroll
        for (int i = 0; i < 8; i++) t += red[i];
        rinv = rsqrtf(t / (float)Dv + 1e-6f);
    }
    __syncthreads();
    float r = rinv;
#pragma unroll
    for (int i = 0; i < 4; i++) {
        float val = v[i] * w[tid + i*256] * r;
        bf16 h = __float2bfloat16(val);
        hi[(size_t)row*Dv + tid + i*256] = h;
        lo[(size_t)row*Dv + tid + i*256] = __float2bfloat16(val - __bfloat162float(h));
    }
}

// ---------------- transpose + bf16-split weight (1024x1024) ----------------
__global__ void k_wsplit(const float* __restrict__ W,
                         bf16* __restrict__ Thi, bf16* __restrict__ Tlo) {
    __shared__ float t[32][33];
    int k0 = blockIdx.y * 32, n0 = blockIdx.x * 32;
    int tx = threadIdx.x, ty = threadIdx.y;   // (32, 8)
#pragma unroll
    for (int r = 0; r < 4; r++)
        t[ty + r*8][tx] = W[(size_t)(k0 + ty + r*8)*Dv + n0 + tx];
    __syncthreads();
#pragma unroll
    for (int r = 0; r < 4; r++) {
        float v = t[tx][ty + r*8];
        bf16 h = __float2bfloat16(v);
        size_t off = (size_t)(n0 + ty + r*8)*Dv + k0 + tx;
        Thi[off] = h;
        Tlo[off] = __float2bfloat16(v - __bfloat162float(h));
    }
}

// -------- mma.sync big GEMM: (16384x1024)@(1024x1024), split-head out -------
#define MMA_SMEM (2*65536)
__global__ void __launch_bounds__(256)
k_gemm_mma(const bf16* __restrict__ Ahi, const bf16* __restrict__ Alo,
           const bf16* __restrict__ Bhi, const bf16* __restrict__ Blo,
           float* __restrict__ C) {
    extern __shared__ char smem[];
    uint32_t sb = smem_u32(smem);
    int tid = threadIdx.x;
    int wid = tid >> 5, lane = tid & 31;
    int wm = wid >> 1, wn = wid & 1;          // warps 4(M) x 2(N)
    int m0 = blockIdx.y * 128, n0 = blockIdx.x * 128;

    const bf16* base_l[4] = {
        Ahi + (size_t)m0 * Dv, Alo + (size_t)m0 * Dv,
        Bhi + (size_t)n0 * Dv, Blo + (size_t)n0 * Dv };

#define LOAD_STAGE(CH, ST) do {                                                \
    int _k0 = (CH) * 64;                                                       \
    uint32_t _sb = sb + (ST) * 65536;                                          \
    _Pragma("unroll")                                                          \
    for (int i = 0; i < 16; i++) {                                             \
        int idx = i * 256 + tid;                                               \
        int layer = idx >> 10, rem = idx & 1023;                               \
        int r = rem >> 3, c16 = rem & 7;                                       \
        const bf16* src = base_l[layer] + (size_t)r * Dv + _k0 + c16 * 8;      \
        uint32_t dst = _sb + layer * 16384 + r * 128 + (((c16 ^ (r & 7))) << 4); \
        cp16(dst, src);                                                        \
    }                                                                          \
    asm volatile("cp.async.commit_group;" ::: "memory");                       \
} while (0)

    LOAD_STAGE(0, 0);

    float acc[2][8][4];
#pragma unroll
    for (int mt = 0; mt < 2; mt++)
#pragma unroll
        for (int nt = 0; nt < 8; nt++)
#pragma unroll
            for (int e = 0; e < 4; e++) acc[mt][nt][e] = 0.f;

    for (int ch = 0; ch < 16; ch++) {
        if (ch < 15) {
            LOAD_STAGE(ch + 1, (ch + 1) & 1);
            asm volatile("cp.async.wait_group 1;" ::: "memory");
        } else {
            asm volatile("cp.async.wait_group 0;" ::: "memory");
        }
        __syncthreads();

        uint32_t sA = sb + (ch & 1) * 65536;
        uint32_t sB = sA + 32768;
#pragma unroll
        for (int kk = 0; kk < 4; kk++) {
            uint32_t a_hi[2][4], a_lo[2][4];
#pragma unroll
            for (int mt = 0; mt < 2; mt++) {
                int r = wm*32 + mt*16 + (lane & 7) + ((lane >> 3) & 1) * 8;
                int cch = kk*2 + (lane >> 4);
                uint32_t off = r * 128 + (((cch ^ (r & 7))) << 4);
                ldsm4(a_hi[mt], sA + off);
                ldsm4(a_lo[mt], sA + 16384 + off);
            }
            uint32_t b_hi[8][2], b_lo[8][2];
#pragma unroll
            for (int np = 0; np < 4; np++) {
                int r = wn*64 + np*16 + (lane & 7) + ((lane >> 4) & 1) * 8;
                int cch = kk*2 + ((lane >> 3) & 1);
                uint32_t off = r * 128 + (((cch ^ (r & 7))) << 4);
                uint32_t d[4];
                ldsm4(d, sB + off);
                b_hi[2*np][0] = d[0]; b_hi[2*np][1] = d[1];
                b_hi[2*np+1][0] = d[2]; b_hi[2*np+1][1] = d[3];
                ldsm4(d, sB + 16384 + off);
                b_lo[2*np][0] = d[0]; b_lo[2*np][1] = d[1];
                b_lo[2*np+1][0] = d[2]; b_lo[2*np+1][1] = d[3];
            }
#pragma unroll
            for (int mt = 0; mt < 2; mt++)
#pragma unroll
                for (int nt = 0; nt < 8; nt++) {
                    MmaOp<bf16>::run(acc[mt][nt], a_hi[mt], b_hi[nt]);
                    MmaOp<bf16>::run(acc[mt][nt], a_hi[mt], b_lo[nt]);
                    MmaOp<bf16>::run(acc[mt][nt], a_lo[mt], b_hi[nt]);
                }
        }
        __syncthreads();
    }

    int b = m0 >> 11;
#pragma unroll
    for (int mt = 0; mt < 2; mt++) {
        int mrow = m0 + wm*32 + mt*16 + (lane >> 2);
        int s = mrow & 2047;
#pragma unroll
        for (int nt = 0; nt < 8; nt++) {
            int col = n0 + wn*64 + nt*8 + (lane & 3) * 2;
            int h = col >> 6, hd = col & 63;
            size_t ob = (((size_t)(b*Hv + h))*Sv) * 64 + (size_t)hd;
            *(float2*)&C[ob + (size_t)s*64]       = make_float2(acc[mt][nt][0], acc[mt][nt][1]);
            *(float2*)&C[ob + (size_t)(s + 8)*64] = make_float2(acc[mt][nt][2], acc[mt][nt][3]);
        }
    }
#undef LOAD_STAGE
}

// -------------- rmsnorm64: keys -> fp16 normed --------------
__global__ void k_rmsnorm64k(const float* __restrict__ x, const float* __restrict__ w,
                             f16* __restrict__ ob) {
    int r = blockIdx.x * 8 + (threadIdx.x >> 5);
    int lane = threadIdx.x & 31;
    const float* xr = x + (size_t)r * 64;
    float a = xr[lane], b = xr[lane + 32];
    float ss = a*a + b*b;
#pragma unroll
    for (int o = 16; o > 0; o >>= 1) ss += __shfl_xor_sync(0xffffffffu, ss, o);
    float rr = rsqrtf(ss / 64.f + 1e-6f);
    ob[(size_t)r*64 + lane]      = __float2half(a * w[lane]      * rr);
    ob[(size_t)r*64 + lane + 32] = __float2half(b * w[lane + 32] * rr);
}

// -------------- rmsnorm64: q -> fp32 in place + bf16 hi/lo split ------------
__global__ void k_rmsnorm64q(float* __restrict__ x, const float* __restrict__ w,
                             bf16* __restrict__ ohi, bf16* __restrict__ olo) {
    int r = blockIdx.x * 8 + (threadIdx.x >> 5);
    int lane = threadIdx.x & 31;
    float* xr = x + (size_t)r * 64;
    float a = xr[lane], b = xr[lane + 32];
    float ss = a*a + b*b;
#pragma unroll
    for (int o = 16; o > 0; o >>= 1) ss += __shfl_xor_sync(0xffffffffu, ss, o);
    float rr = rsqrtf(ss / 64.f + 1e-6f);
    float v0 = a * w[lane] * rr, v1 = b * w[lane + 32] * rr;
    xr[lane] = v0; xr[lane + 32] = v1;
    bf16 h0 = __float2bfloat16(v0), h1 = __float2bfloat16(v1);
    size_t base = (size_t)r * 64;
    ohi[base + lane] = h0;      olo[base + lane]      = __float2bfloat16(v0 - __bfloat162float(h0));
    ohi[base + lane + 32] = h1; olo[base + lane + 32] = __float2bfloat16(v1 - __bfloat162float(h1));
}

// ======== MLP GEMM 1: C[MT,256] = A[MT,64] @ B[256,64]^T (B K-major) ========
// MODE 0 (T=f16): store fwd -> o1 = pre, o2 = gelu(pre).
// MODE 1 (T=f16): dh0       -> o1 = acc * gelu'(o2=pre0).
// MODE 2 (T=bf16): retrieve -> 3-term split; o1 = hi(gelu), o2 = lo(gelu).
template <int MODE, typename T>
__global__ void __launch_bounds__(256)
k_mlp0(const T* __restrict__ Ahi, const T* __restrict__ Alo,
       const T* __restrict__ Bhi, const T* __restrict__ Blo,
       long long ws, T* __restrict__ o1, T* __restrict__ o2) {
    extern __shared__ char sm[];
    uint32_t sb = smem_u32(sm);
    constexpr uint32_t SB = (MODE == 2) ? 16384u : 8192u;
    int tid = threadIdx.x, wid = tid >> 5, lane = tid & 31;
    int wm = wid >> 2, wn = wid & 3;          // 2(M) x 4(N)
    int m0 = blockIdx.x * 64;
    int bh = m0 >> 11;

    {
        const T* Ab = Ahi + (size_t)m0 * 64;
#pragma unroll
        for (int i = 0; i < 2; i++) {
            int idx = i*256 + tid; int r = idx >> 3, g = idx & 7;
            cp16(sb + r*128 + ((g ^ (r & 7)) << 4), Ab + r*64 + g*8);
        }
        if (MODE == 2) {
            const T* A2 = Alo + (size_t)m0 * 64;
#pragma unroll
            for (int i = 0; i < 2; i++) {
                int idx = i*256 + tid; int r = idx >> 3, g = idx & 7;
                cp16(sb + 8192 + r*128 + ((g ^ (r & 7)) << 4), A2 + r*64 + g*8);
            }
        }
        const T* Bb = Bhi + (size_t)bh * ws;
#pragma unroll
        for (int i = 0; i < 8; i++) {
            int idx = i*256 + tid; int r = idx >> 3, g = idx & 7;
            cp16(sb + SB + r*128 + ((g ^ (r & 7)) << 4), Bb + r*64 + g*8);
        }
        if (MODE == 2) {
            const T* B2 = Blo + (size_t)bh * ws;
#pragma unroll
            for (int i = 0; i < 8; i++) {
                int idx = i*256 + tid; int r = idx >> 3, g = idx & 7;
                cp16(sb + SB + 32768 + r*128 + ((g ^ (r & 7)) << 4), B2 + r*64 + g*8);
            }
        }
    }
    asm volatile("cp.async.commit_group;\ncp.async.wait_group 0;" ::: "memory");
    __syncthreads();

    float acc[2][8][4];
#pragma unroll
    for (int mt = 0; mt < 2; mt++)
#pragma unroll
        for (int nt = 0; nt < 8; nt++)
#pragma unroll
            for (int e = 0; e < 4; e++) acc[mt][nt][e] = 0.f;

#pragma unroll
    for (int kk = 0; kk < 4; kk++) {
        uint32_t ah[2][4], al[2][4];
#pragma unroll
        for (int mt = 0; mt < 2; mt++) {
            int r = wm*32 + mt*16 + (lane & 7) + ((lane >> 3) & 1) * 8;
            int cch = kk*2 + (lane >> 4);
            uint32_t off = r*128 + ((cch ^ (r & 7)) << 4);
            ldsm4(ah[mt], sb + off);
            if (MODE == 2) ldsm4(al[mt], sb + 8192 + off);
        }
        uint32_t bh_r[8][2], bl_r[8][2];
#pragma unroll
        for (int np = 0; np < 4; np++) {
            int r = wn*64 + np*16 + (lane & 7) + ((lane >> 4) & 1) * 8;
            int cch = kk*2 + ((lane >> 3) & 1);
            uint32_t off = r*128 + ((cch ^ (r & 7)) << 4);
            uint32_t d[4];
            ldsm4(d, sb + SB + off);
            bh_r[2*np][0]=d[0]; bh_r[2*np][1]=d[1];
            bh_r[2*np+1][0]=d[2]; bh_r[2*np+1][1]=d[3];
            if (MODE == 2) {
                ldsm4(d, sb + SB + 32768 + off);
                bl_r[2*np][0]=d[0]; bl_r[2*np][1]=d[1];
                bl_r[2*np+1][0]=d[2]; bl_r[2*np+1][1]=d[3];
            }
        }
#pragma unroll
        for (int mt = 0; mt < 2; mt++)
#pragma unroll
            for (int nt = 0; nt < 8; nt++) {
                MmaOp<T>::run(acc[mt][nt], ah[mt], bh_r[nt]);
                if (MODE == 2) {
                    MmaOp<T>::run(acc[mt][nt], ah[mt], bl_r[nt]);
                    MmaOp<T>::run(acc[mt][nt], al[mt], bh_r[nt]);
                }
            }
    }

#pragma unroll
    for (int mt = 0; mt < 2; mt++) {
        int mrow = m0 + wm*32 + mt*16 + (lane >> 2);
#pragma unroll
        for (int nt = 0; nt < 8; nt++) {
            int c = wn*64 + nt*8 + (lane & 3) * 2;
#pragma unroll
            for (int half = 0; half < 2; half++) {
                size_t off = (size_t)(mrow + half*8) * 256 + c;
                float v0 = acc[mt][nt][half*2], v1 = acc[mt][nt][half*2 + 1];
                if (MODE == 0) {
                    o1[off] = fromf<T>(v0);          o1[off+1] = fromf<T>(v1);
                    o2[off] = fromf<T>(geluf(v0));   o2[off+1] = fromf<T>(geluf(v1));
                } else if (MODE == 1) {
                    float p0 = tof(o2[off]), p1 = tof(o2[off+1]);
                    o1[off]   = fromf<T>(v0 * gelugrad(p0));
                    o1[off+1] = fromf<T>(v1 * gelugrad(p1));
                } else {
                    float gl0 = geluf(v0), gl1 = geluf(v1);
                    T h0 = fromf<T>(gl0), h1 = fromf<T>(gl1);
                    o1[off] = h0; o1[off+1] = h1;
                    o2[off]   = fromf<T>(gl0 - tof(h0));
                    o2[off+1] = fromf<T>(gl1 - tof(h1));
                }
            }
        }
    }
}

// ======== MLP GEMM 2: C[MT,64] fp32 = A[MT,256] @ B[64,256]^T ==============
// MODE 0 (T=f16): store (plain). MODE 1 (T=bf16): retrieve (3-term split).
template <int MODE, typename T>
__global__ void __launch_bounds__(256)
k_mlp1(const T* __restrict__ Ahi, const T* __restrict__ Alo,
       const T* __restrict__ Bhi, const T* __restrict__ Blo,
       long long ws, float* __restrict__ Cout) {
    extern __shared__ char sm[];
    uint32_t sb = smem_u32(sm);
    constexpr uint32_t SB = (MODE == 1) ? 65536u : 32768u;
    constexpr uint32_t ASTRIDE = (MODE == 1) ? 32768u : 16384u;
    int tid = threadIdx.x, wid = tid >> 5, lane = tid & 31;
    int wm = wid >> 1, wn = wid & 1;          // 4(M) x 2(N)
    int m0 = blockIdx.x * 128;
    int bh = m0 >> 11;

    {   // B: [64][256] all-K resident
        const T* Bb = Bhi + (size_t)bh * ws;
#pragma unroll
        for (int i = 0; i < 8; i++) {
            int idx = i*256 + tid; int r = idx >> 5, g = idx & 31;
            cp16(sb + SB + r*512 + ((g ^ (r & 7)) << 4), Bb + r*256 + g*8);
        }
        if (MODE == 1) {
            const T* B2 = Blo + (size_t)bh * ws;
#pragma unroll
            for (int i = 0; i < 8; i++) {
                int idx = i*256 + tid; int r = idx >> 5, g = idx & 31;
                cp16(sb + SB + 32768 + r*512 + ((g ^ (r & 7)) << 4), B2 + r*256 + g*8);
            }
        }
    }
#define LA(CH, ST) do {                                                        \
    uint32_t _a = sb + (ST) * ASTRIDE;                                         \
    _Pragma("unroll")                                                          \
    for (int i = 0; i < 4; i++) {                                              \
        int idx = i*256 + tid; int r = idx >> 3, g = idx & 7;                  \
        cp16(_a + r*128 + ((g ^ (r & 7)) << 4),                                \
             Ahi + (size_t)(m0 + r)*256 + (CH)*64 + g*8);                      \
        if (MODE == 1)                                                         \
            cp16(_a + 16384 + r*128 + ((g ^ (r & 7)) << 4),                    \
                 Alo + (size_t)(m0 + r)*256 + (CH)*64 + g*8);                  \
    }                                                                          \
    asm volatile("cp.async.commit_group;" ::: "memory");                       \
} while (0)

    LA(0, 0);

    float acc[2][4][4];
#pragma unroll
    for (int mt = 0; mt < 2; mt++)
#pragma unroll
        for (int nt = 0; nt < 4; nt++)
#pragma unroll
            for (int e = 0; e < 4; e++) acc[mt][nt][e] = 0.f;

    for (int ch = 0; ch < 4; ch++) {
        if (ch < 3) {
            LA(ch + 1, (ch + 1) & 1);
            asm volatile("cp.async.wait_group 1;" ::: "memory");
        } else {
            asm volatile("cp.async.wait_group 0;" ::: "memory");
        }
        __syncthreads();
        uint32_t sA = sb + (ch & 1) * ASTRIDE;
#pragma unroll
        for (int kk = 0; kk < 4; kk++) {
            uint32_t ah[2][4], al[2][4];
#pragma unroll
            for (int mt = 0; mt < 2; mt++) {
                int r = wm*32 + mt*16 + (lane & 7) + ((lane >> 3) & 1) * 8;
                int cch = kk*2 + (lane >> 4);
                uint32_t off = r*128 + ((cch ^ (r & 7)) << 4);
                ldsm4(ah[mt], sA + off);
                if (MODE == 1) ldsm4(al[mt], sA + 16384 + off);
            }
            uint32_t bh_r[4][2], bl_r[4][2];
#pragma unroll
            for (int np = 0; np < 2; np++) {
                int r = wn*32 + np*16 + (lane & 7) + ((lane >> 4) & 1) * 8;
                int kg = ch*8 + kk*2 + ((lane >> 3) & 1);
                uint32_t off = r*512 + ((kg ^ (r & 7)) << 4);
                uint32_t d[4];
                ldsm4(d, sb + SB + off);
                bh_r[2*np][0]=d[0]; bh_r[2*np][1]=d[1];
                bh_r[2*np+1][0]=d[2]; bh_r[2*np+1][1]=d[3];
                if (MODE == 1) {
                    ldsm4(d, sb + SB + 32768 + off);
                    bl_r[2*np][0]=d[0]; bl_r[2*np][1]=d[1];
                    bl_r[2*np+1][0]=d[2]; bl_r[2*np+1][1]=d[3];
                }
            }
#pragma unroll
            for (int mt = 0; mt < 2; mt++)
#pragma unroll
                for (int nt = 0; nt < 4; nt++) {
                    MmaOp<T>::run(acc[mt][nt], ah[mt], bh_r[nt]);
                    if (MODE == 1) {
                        MmaOp<T>::run(acc[mt][nt], ah[mt], bl_r[nt]);
                        MmaOp<T>::run(acc[mt][nt], al[mt], bh_r[nt]);
                    }
                }
        }
        __syncthreads();
    }
#pragma unroll
    for (int mt = 0; mt < 2; mt++) {
        int mrow = m0 + wm*32 + mt*16 + (lane >> 2);
#pragma unroll
        for (int nt = 0; nt < 4; nt++) {
            int c = wn*32 + nt*8 + (lane & 3) * 2;
            *(float2*)&Cout[(size_t)mrow*64 + c]     = make_float2(acc[mt][nt][0], acc[mt][nt][1]);
            *(float2*)&Cout[(size_t)(mrow+8)*64 + c] = make_float2(acc[mt][nt][2], acc[mt][nt][3]);
        }
    }
#undef LA
}

// ======== gradT: G[bh][MI][NO] = sum_s A[bh*S+s][MI-col] * B[bh*S+s][NO-col]
template <int MI, int NO>
__global__ void __launch_bounds__(256)
k_gradmma(const f16* __restrict__ A, const f16* __restrict__ Bm,
          float* __restrict__ G) {
    __shared__ __align__(16) char sm[32768];   // A st*8192, B 16384+st*8192
    uint32_t sb = smem_u32(sm);
    int tid = threadIdx.x, wid = tid >> 5, lane = tid & 31;
    int wm = wid >> 2, wn = wid & 3;           // 2(M) x 4(N), tile 64x64
    int bh = blockIdx.z;
    int m0 = blockIdx.y * 64, n0 = blockIdx.x * 64;
    const f16* Ab = A  + ((size_t)bh * Sv) * MI + m0;
    const f16* Bb = Bm + ((size_t)bh * Sv) * NO + n0;

#define LG(ST, S0) do {                                                        \
    _Pragma("unroll")                                                          \
    for (int i = 0; i < 2; i++) {                                              \
        int idx = i*256 + tid; int r = idx >> 3, g = idx & 7;                  \
        cp16(sb + (ST)*8192 + r*128 + ((g ^ (r & 7)) << 4),                    \
             Ab + (size_t)((S0) + r)*MI + g*8);                                \
        cp16(sb + 16384 + (ST)*8192 + r*128 + ((g ^ (r & 7)) << 4),            \
             Bb + (size_t)((S0) + r)*NO + g*8);                                \
    }                                                                          \
    asm volatile("cp.async.commit_group;" ::: "memory");                       \
} while (0)

    LG(0, 0);
    float acc[2][2][4];
#pragma unroll
    for (int mt = 0; mt < 2; mt++)
#pragma unroll
        for (int nt = 0; nt < 2; nt++)
#pragma unroll
            for (int e = 0; e < 4; e++) acc[mt][nt][e] = 0.f;

    for (int st = 0; st < 32; st++) {
        if (st < 31) {
            LG((st + 1) & 1, (st + 1) * 64);
            asm volatile("cp.async.wait_group 1;" ::: "memory");
        } else {
            asm volatile("cp.async.wait_group 0;" ::: "memory");
        }
        __syncthreads();
        uint32_t sA = sb + (st & 1) * 8192;
        uint32_t sB = sb + 16384 + (st & 1) * 8192;
#pragma unroll
        for (int kk = 0; kk < 4; kk++) {
            uint32_t aT[2][4];
#pragma unroll
            for (int mt = 0; mt < 2; mt++) {
                int row = kk*16 + (lane & 7) + ((lane >> 4) & 1) * 8;
                int cg = wm*4 + mt*2 + ((lane >> 3) & 1);
                ldsm4t(aT[mt], sA + row*128 + ((cg ^ (row & 7)) << 4));
            }
            int row = kk*16 + (lane & 7) + ((lane >> 3) & 1) * 8;
            int cg = wn*2 + (lane >> 4);
            uint32_t d[4];
            ldsm4t(d, sB + row*128 + ((cg ^ (row & 7)) << 4));
            uint32_t bT[2][2] = {{d[0], d[1]}, {d[2], d[3]}};
#pragma unroll
            for (int mt = 0; mt < 2; mt++)
#pragma unroll
                for (int nt = 0; nt < 2; nt++)
                    MmaOp<f16>::run(acc[mt][nt], aT[mt], bT[nt]);
        }
        __syncthreads();
    }
#pragma unroll
    for (int mt = 0; mt < 2; mt++) {
        int m = m0 + wm*32 + mt*16 + (lane >> 2);
#pragma unroll
        for (int nt = 0; nt < 2; nt++) {
            int n = n0 + wn*16 + nt*8 + (lane & 3) * 2;
            *(float2*)&G[((size_t)bh*MI + m)*NO + n]     = make_float2(acc[mt][nt][0], acc[mt][nt][1]);
            *(float2*)&G[((size_t)bh*MI + m + 8)*NO + n] = make_float2(acc[mt][nt][2], acc[mt][nt][3]);
        }
    }
#undef LG
}

// ---------- fused pf_rmsnorm fwd+bwd for the store loss gradient ------------
__global__ void k_dh(const f16* __restrict__ keysb, f16* __restrict__ dhb) {
    int r = blockIdx.x * 8 + (threadIdx.x >> 5);
    int lane = threadIdx.x & 31;
    size_t base = (size_t)r * 64;
    float h0 = g_pre1[base + lane], h1 = g_pre1[base + lane + 32];
    float ss = h0*h0 + h1*h1;
#pragma unroll
    for (int o = 16; o > 0; o >>= 1) ss += __shfl_xor_sync(0xffffffffu, ss, o);
    float rms = sqrtf(ss / 64.f + 1e-8f);
    float hn0 = h0 / rms, hn1 = h1 / rms;
    float t = g_theta[r];
    float k0 = __half2float(keysb[base + lane]);
    float k1 = __half2float(keysb[base + lane + 32]);
    float dp0 = 2.f * t * ((hn0 + k0) - g_values[base + lane]);
    float dp1 = 2.f * t * ((hn1 + k1) - g_values[base + lane + 32]);
    float dy = dp0*hn0 + dp1*hn1;
#pragma unroll
    for (int o = 16; o > 0; o >>= 1) dy += __shfl_xor_sync(0xffffffffu, dy, o);
    dhb[base + lane]      = __float2half((dp0 - hn0 * dy / 64.f) / rms);
    dhb[base + lane + 32] = __float2half((dp1 - hn1 * dy / 64.f) / rms);
}

// ---------------- gates: alpha, theta ---------------------------------------
__global__ void __launch_bounds__(256)
k_gates(const float* __restrict__ aw, const float* __restrict__ ab,
        const float* __restrict__ tw, const float* __restrict__ tb) {
    __shared__ float Xs[64][128];
    __shared__ float Ws[64][32];
    int m0 = blockIdx.x * 128;
    int tid = threadIdx.x;
    int rg = tid >> 3, cg = tid & 7;
    float acc[4][4] = {};
    for (int k0 = 0; k0 < 1024; k0 += 64) {
#pragma unroll
        for (int i = 0; i < 4; i++) {
            int idx = tid + i*256;
            int r = idx >> 3, c8 = idx & 7;
            size_t ga = (size_t)(m0 + r)*1024 + k0 + c8*8;
            uint4 vh = *(const uint4*)&g_xnhi[ga];
            uint4 vl = *(const uint4*)&g_xnlo[ga];
            __nv_bfloat162 h2[4], l2[4];
            *(uint4*)h2 = vh; *(uint4*)l2 = vl;
#pragma unroll
            for (int j = 0; j < 4; j++) {
                float2 fh = __bfloat1622float2(h2[j]);
                float2 fl = __bfloat1622float2(l2[j]);
                Xs[c8*8 + 2*j][r]     = fh.x + fl.x;
                Xs[c8*8 + 2*j + 1][r] = fh.y + fl.y;
            }
        }
#pragma unroll
        for (int i = 0; i < 2; i++) {
            int idx = tid + i*256;
            int r = idx >> 3, c4 = idx & 7;
            const float* src = (c4 < 4) ? (aw + (size_t)(k0 + r)*16 + c4*4)
                                        : (tw + (size_t)(k0 + r)*16 + (c4 - 4)*4);
            *(float4*)&Ws[r][c4*4] = *(const float4*)src;
        }
        __syncthreads();
#pragma unroll
        for (int k = 0; k < 64; k++) {
            float ra[4], rb[4];
#pragma unroll
            for (int i = 0; i < 4; i++) ra[i] = Xs[k][rg*4 + i];
#pragma unroll
            for (int j = 0; j < 4; j++) rb[j] = Ws[k][cg*4 + j];
#pragma unroll
            for (int i = 0; i < 4; i++)
#pragma unroll
                for (int j = 0; j < 4; j++) acc[i][j] += ra[i] * rb[j];
        }
        __syncthreads();
    }
#pragma unroll
    for (int i = 0; i < 4; i++) {
        int m = m0 + rg*4 + i;
        int b = m >> 11, s = m & 2047;
#pragma unroll
        for (int j = 0; j < 4; j++) {
            int c = cg*4 + j;
            int h = c & 15;
            size_t off = ((size_t)(b*Hv + h))*Sv + s;
            if (c < 16) g_alpha[off] = 1.f / (1.f + expf(-(acc[i][j] + ab[h])));
            else        g_theta[off] = 0.01f / (1.f + expf(-(acc[i][j] + tb[h])));
        }
    }
}

// ---------------- per-bh reductions -----------------------------------------
__global__ void k_amean() {
    int bh = blockIdx.x; int tid = threadIdx.x;
    float s = 0.f;
    for (int i = tid; i < Sv; i += 256) s += g_alpha[(size_t)bh*Sv + i];
#pragma unroll
    for (int o = 16; o > 0; o >>= 1) s += __shfl_xor_sync(0xffffffffu, s, o);
    __shared__ float red[8];
    if ((tid & 31) == 0) red[tid >> 5] = s;
    __syncthreads();
    if (tid == 0) {
        float t = 0.f;
#pragma unroll
        for (int i = 0; i < 8; i++) t += red[i];
        g_amean[bh] = t / (float)Sv;
    }
}

__global__ void k_clip() {
    int bh = blockIdx.x; int tid = threadIdx.x;
    const float* a = g_g0 + (size_t)bh * 16384;
    const float* b = g_g1 + (size_t)bh * 16384;
    float s = 0.f;
    for (int i = tid; i < 16384; i += 256) {
        float v = a[i]; s += v*v;
        v = b[i]; s += v*v;
    }
#pragma unroll
    for (int o = 16; o > 0; o >>= 1) s += __shfl_xor_sync(0xffffffffu, s, o);
    __shared__ float red[8];
    if ((tid & 31) == 0) red[tid >> 5] = s;
    __syncthreads();
    if (tid == 0) {
        float t = 0.f;
#pragma unroll
        for (int i = 0; i < 8; i++) t += red[i];
        float c = 10.f / (sqrtf(t) + 1e-6f);
        g_coef[bh] = c < 1.f ? c : 1.f;
    }
}

// ---------------- weight prep + update --------------------------------------
__global__ void k_tr(const float* __restrict__ src, float* __restrict__ dstF,
                     f16* __restrict__ dstB, int R, int C) {
    int idx = blockIdx.x * 256 + threadIdx.x;
    if (idx >= R*C) return;
    int c = idx / R, r = idx % R;             // dst is [C][R]
    float v = src[r*C + c];
    dstF[idx] = v;
    dstB[idx] = __float2half(v);
}
__global__ void k_cpb(const float* __restrict__ s, f16* __restrict__ d, int n) {
    int idx = blockIdx.x * 256 + threadIdx.x;
    if (idx < n) d[idx] = __float2half(s[idx]);
}
__global__ void k_newwT(const float* __restrict__ WT, const float* __restrict__ gT,
                        bf16* __restrict__ ohi, bf16* __restrict__ olo) {
    size_t idx = (size_t)blockIdx.x * 256 + threadIdx.x;
    int bh = (int)(idx >> 14); int e = (int)(idx & 16383);
    float w = WT[e];
    float nw = (1.f - g_amean[bh]) * w - g_coef[bh] * gT[idx];
    if (!isfinite(nw)) nw = w;
    bf16 h = __float2bfloat16(nw);
    ohi[idx] = h;
    olo[idx] = __float2bfloat16(nw - __bfloat162float(h));
}

// ---------------- retrieve epilogue -----------------------------------------
__global__ void k_final(float* __restrict__ out) {
    int r = blockIdx.x * 8 + (threadIdx.x >> 5);
    int lane = threadIdx.x & 31;
    size_t base = (size_t)r * 64;
    float h0 = g_pre1[base + lane], h1 = g_pre1[base + lane + 32];
    if (!isfinite(h0)) h0 = 0.f;
    if (!isfinite(h1)) h1 = 0.f;
    float ss = h0*h0 + h1*h1;
#pragma unroll
    for (int o = 16; o > 0; o >>= 1) ss += __shfl_xor_sync(0xffffffffu, ss, o);
    float rms = sqrtf(ss / 64.f + 1e-8f);
    float o0 = h0 / rms + g_q[base + lane];
    float o1 = h1 / rms + g_q[base + lane + 32];
    int bh = r >> 11, s = r & 2047;
    int b = bh >> 4, hh = bh & 15;
    size_t ob = ((size_t)(b*Sv + s))*Dv + hh*64;
    out[ob + lane]      = o0;
    out[ob + lane + 32] = o1;
}

// ============================================================================
extern "C" void kernel_launch(void* const* d_in, const int* in_sizes, int n_in,
                              void* d_out, int out_size) {
    (void)in_sizes; (void)n_in; (void)out_size;
    const float* x   = (const float*)d_in[0];
    const float* W_K = (const float*)d_in[1];
    const float* W_V = (const float*)d_in[2];
    const float* W_Q = (const float*)d_in[3];
    const float* mW0 = (const float*)d_in[4];
    const float* mW1 = (const float*)d_in[5];
    const float* knw = (const float*)d_in[6];
    const float* qnw = (const float*)d_in[7];
    const float* snw = (const float*)d_in[8];
    const float* rnw = (const float*)d_in[9];
    const float* aw  = (const float*)d_in[10];
    const float* ab  = (const float*)d_in[11];
    const float* tw  = (const float*)d_in[12];
    const float* tb  = (const float*)d_in[13];
    float* out = (float*)d_out;

    bf16 *xnhi, *xnlo, *wthi, *wtlo, *qhi, *qlo;
    bf16 *nW0Thi, *nW0Tlo, *nW1Thi, *nW1Tlo;
    f16 *keysb, *dhb, *mW0Tb, *mW1Tb, *mW1b;
    float *keys, *values, *q, *pre1, *g0p, *g1p, *mW0T, *mW1T;
    char* pool;
    cudaGetSymbolAddress((void**)&xnhi,   g_xnhi);
    cudaGetSymbolAddress((void**)&xnlo,   g_xnlo);
    cudaGetSymbolAddress((void**)&wthi,   g_wthi);
    cudaGetSymbolAddress((void**)&wtlo,   g_wtlo);
    cudaGetSymbolAddress((void**)&keys,   g_keys);
    cudaGetSymbolAddress((void**)&values, g_values);
    cudaGetSymbolAddress((void**)&q,      g_q);
    cudaGetSymbolAddress((void**)&pre1,   g_pre1);
    cudaGetSymbolAddress((void**)&keysb,  g_keysb);
    cudaGetSymbolAddress((void**)&qhi,    g_qhi);
    cudaGetSymbolAddress((void**)&qlo,    g_qlo);
    cudaGetSymbolAddress((void**)&dhb,    g_dhb);
    cudaGetSymbolAddress((void**)&pool,   g_pool);
    cudaGetSymbolAddress((void**)&g0p,    g_g0);
    cudaGetSymbolAddress((void**)&g1p,    g_g1);
    cudaGetSymbolAddress((void**)&mW0T,   g_mW0T);
    cudaGetSymbolAddress((void**)&mW1T,   g_mW1T);
    cudaGetSymbolAddress((void**)&mW0Tb,  g_mW0Tb);
    cudaGetSymbolAddress((void**)&mW1Tb,  g_mW1Tb);
    cudaGetSymbolAddress((void**)&mW1b,   g_mW1b);
    cudaGetSymbolAddress((void**)&nW0Thi, g_nW0Thi);
    cudaGetSymbolAddress((void**)&nW0Tlo, g_nW0Tlo);
    cudaGetSymbolAddress((void**)&nW1Thi, g_nW1Thi);
    cudaGetSymbolAddress((void**)&nW1Tlo, g_nW1Tlo);

    f16* pre0h = (f16*)(pool);
    f16* h1h   = (f16*)(pool + 134217728);
    f16* dh0h  = (f16*)(pool + 268435456);
    bf16* h1rhi = (bf16*)(pool);              // aliases pre0h (dead by then)
    bf16* h1rlo = (bf16*)(pool + 268435456);  // aliases dh0h (dead by then)

    cudaFuncSetAttribute(k_gemm_mma, cudaFuncAttributeMaxDynamicSharedMemorySize, MMA_SMEM);
    cudaFuncSetAttribute((k_mlp0<0, f16>), cudaFuncAttributeMaxDynamicSharedMemorySize, 40960);
    cudaFuncSetAttribute((k_mlp0<1, f16>), cudaFuncAttributeMaxDynamicSharedMemorySize, 40960);
    cudaFuncSetAttribute((k_mlp0<2, bf16>), cudaFuncAttributeMaxDynamicSharedMemorySize, 81920);
    cudaFuncSetAttribute((k_mlp1<0, f16>), cudaFuncAttributeMaxDynamicSharedMemorySize, 65536);
    cudaFuncSetAttribute((k_mlp1<1, bf16>), cudaFuncAttributeMaxDynamicSharedMemorySize, 131072);

    dim3 gtc(8, 128);
    dim3 gws(32, 32), bws(32, 8);

    // ---- weight prep (independent) ----
    k_tr<<<64, 256>>>(mW0, mW0T, mW0Tb, HDv, HIDv);   // -> [256][64]
    k_tr<<<64, 256>>>(mW1, mW1T, mW1Tb, HIDv, HDv);   // -> [64][256]
    k_cpb<<<64, 256>>>(mW1, mW1b, HIDv*HDv);

    // ---- store path ----
    k_rmsnorm_split<<<Mv, 256>>>(x, snw, xnhi, xnlo);
    k_wsplit<<<gws, bws>>>(W_K, wthi, wtlo);
    k_gemm_mma<<<gtc, 256, MMA_SMEM>>>(xnhi, xnlo, wthi, wtlo, keys);
    k_wsplit<<<gws, bws>>>(W_V, wthi, wtlo);
    k_gemm_mma<<<gtc, 256, MMA_SMEM>>>(xnhi, xnlo, wthi, wtlo, values);
    k_rmsnorm64k<<<MTv/8, 256>>>(keys, knw, keysb);
    k_gates<<<Mv/128, 256>>>(aw, ab, tw, tb);
    k_amean<<<BHv, 256>>>();

    k_mlp0<0, f16><<<MTv/64, 256, 40960>>>(keysb, nullptr, mW0Tb, nullptr, 0, pre0h, h1h);
    k_mlp1<0, f16><<<MTv/128, 256, 65536>>>(h1h, nullptr, mW1Tb, nullptr, 0, pre1);
    k_dh<<<MTv/8, 256>>>(keysb, dhb);
    // dh0 written in place over pre0h (same-thread same-offset read/write)
    k_mlp0<1, f16><<<MTv/64, 256, 40960>>>(dhb, nullptr, mW1b, nullptr, 0, dh0h, pre0h);

    k_gradmma<HDv, HIDv><<<dim3(4, 1, BHv), 256>>>(dhb, h1h, g1p);     // g1^T [64][256]
    k_gradmma<HIDv, HDv><<<dim3(1, 4, BHv), 256>>>(dh0h, keysb, g0p);  // g0^T [256][64]
    k_clip<<<BHv, 256>>>();
    k_newwT<<<(BHv*16384)/256, 256>>>(mW0T, g0p, nW0Thi, nW0Tlo);
    k_newwT<<<(BHv*16384)/256, 256>>>(mW1T, g1p, nW1Thi, nW1Tlo);

    // ---- retrieve path ----
    k_rmsnorm_split<<<Mv, 256>>>(x, rnw, xnhi, xnlo);
    k_wsplit<<<gws, bws>>>(W_Q, wthi, wtlo);
    k_gemm_mma<<<gtc, 256, MMA_SMEM>>>(xnhi, xnlo, wthi, wtlo, q);
    k_rmsnorm64q<<<MTv/8, 256>>>(q, qnw, qhi, qlo);
    k_mlp0<2, bf16><<<MTv/64, 256, 81920>>>(qhi, qlo, nW0Thi, nW0Tlo,
                                            (long long)HIDv*HDv, h1rhi, h1rlo);
    k_mlp1<1, bf16><<<MTv/128, 256, 131072>>>(h1rhi, h1rlo, nW1Thi, nW1Tlo,
                                              (long long)HDv*HIDv, pre1);
    k_final<<<MTv/8, 256>>>(out);
}